// round 1
// baseline (speedup 1.0000x reference)
#include <cuda_runtime.h>
#include <math.h>

#define NB 4
#define LQ 2048
#define EE 1024
#define HH 16
#define DD 64
#define NL (NB*LQ)   /* 8192 */
#define GK EE        /* 1024 */

// Scratch (allocation-free rule: __device__ globals)
__device__ float g_q[(size_t)NB*HH*LQ*DD];
__device__ float g_k[(size_t)NB*HH*LQ*DD];
__device__ float g_v[(size_t)NB*HH*LQ*DD];
__device__ float g_att[(size_t)NB*LQ*EE];

// ---------------------------------------------------------------------------
// C = A @ B^T.  A: [M=8192, K=1024] row-major, B: [1024, K=1024] row-major.
// BM=BN=128, BK=16, 256 threads, 8x8 microtile split into four 4x4 quadrants
// at (tx*4, tx*4+64) so mainloop LDS.128 reads are conflict-free.
// head_major==1: write C[row, col] to [(n*H + col/64)*L + l]*64 + col%64.
// ---------------------------------------------------------------------------
__global__ __launch_bounds__(256, 2)
void gemm_nt(const float* __restrict__ A, const float* __restrict__ B,
             float* __restrict__ C, int head_major)
{
    __shared__ float As[16][128];
    __shared__ float Bs[16][128];
    const int tid = threadIdx.x;
    const int tx = tid & 15, ty = tid >> 4;
    const int row0 = blockIdx.y * 128, col0 = blockIdx.x * 128;
    const int lr = tid >> 2;          // 0..63
    const int lk = (tid & 3) << 2;    // 0,4,8,12

    float acc[2][2][4][4];
#pragma unroll
    for (int qa = 0; qa < 2; qa++)
#pragma unroll
        for (int qb = 0; qb < 2; qb++)
#pragma unroll
            for (int i = 0; i < 4; i++)
#pragma unroll
                for (int j = 0; j < 4; j++) acc[qa][qb][i][j] = 0.f;

    for (int kt = 0; kt < GK; kt += 16) {
#pragma unroll
        for (int s = 0; s < 2; s++) {
            int r = lr + s * 64;
            float4 va = *(const float4*)(A + (size_t)(row0 + r) * GK + kt + lk);
            As[lk + 0][r] = va.x; As[lk + 1][r] = va.y;
            As[lk + 2][r] = va.z; As[lk + 3][r] = va.w;
            float4 vb = *(const float4*)(B + (size_t)(col0 + r) * GK + kt + lk);
            Bs[lk + 0][r] = vb.x; Bs[lk + 1][r] = vb.y;
            Bs[lk + 2][r] = vb.z; Bs[lk + 3][r] = vb.w;
        }
        __syncthreads();
#pragma unroll
        for (int k = 0; k < 16; k++) {
            float4 a0 = *(const float4*)&As[k][ty * 4];
            float4 a1 = *(const float4*)&As[k][ty * 4 + 64];
            float4 b0 = *(const float4*)&Bs[k][tx * 4];
            float4 b1 = *(const float4*)&Bs[k][tx * 4 + 64];
            float av[2][4] = {{a0.x, a0.y, a0.z, a0.w}, {a1.x, a1.y, a1.z, a1.w}};
            float bv[2][4] = {{b0.x, b0.y, b0.z, b0.w}, {b1.x, b1.y, b1.z, b1.w}};
#pragma unroll
            for (int qa = 0; qa < 2; qa++)
#pragma unroll
                for (int qb = 0; qb < 2; qb++)
#pragma unroll
                    for (int i = 0; i < 4; i++)
#pragma unroll
                        for (int j = 0; j < 4; j++)
                            acc[qa][qb][i][j] = fmaf(av[qa][i], bv[qb][j], acc[qa][qb][i][j]);
        }
        __syncthreads();
    }

#pragma unroll
    for (int qa = 0; qa < 2; qa++) {
#pragma unroll
        for (int i = 0; i < 4; i++) {
            int row = row0 + qa * 64 + ty * 4 + i;
#pragma unroll
            for (int qb = 0; qb < 2; qb++) {
                int col = col0 + qb * 64 + tx * 4;
                float4 v = make_float4(acc[qa][qb][i][0], acc[qa][qb][i][1],
                                       acc[qa][qb][i][2], acc[qa][qb][i][3]);
                if (head_major) {
                    int n = row / LQ, l = row % LQ;
                    int h = col / DD, d = col % DD;
                    *(float4*)(C + ((size_t)((n * HH + h) * LQ + l)) * DD + d) = v;
                } else {
                    *(float4*)(C + (size_t)row * EE + col) = v;
                }
            }
        }
    }
}

// ---------------------------------------------------------------------------
// Flash attention, fp32. One block = one (n,h, 64-row q tile).
// Q,K in smem d-major (transposed) -> conflict-free S gemm.
// P row-major (stride 68), V row-major -> conflict-free PV gemm.
// ---------------------------------------------------------------------------
__device__ __forceinline__ float rmax16(float v) {
#pragma unroll
    for (int o = 8; o > 0; o >>= 1) v = fmaxf(v, __shfl_xor_sync(0xffffffffu, v, o, 16));
    return v;
}
__device__ __forceinline__ float rsum16(float v) {
#pragma unroll
    for (int o = 8; o > 0; o >>= 1) v += __shfl_xor_sync(0xffffffffu, v, o, 16);
    return v;
}

#define PSTRIDE 68
#define SMEM_FLASH ((3 * 4096 + 64 * PSTRIDE) * (int)sizeof(float))  /* 66560 B */

__global__ void flash_kernel()
{
    extern __shared__ float sm[];
    float* Qt = sm;            // [64 d][64 q]
    float* Kt = sm + 4096;     // [64 d][64 k]
    float* Vs = sm + 8192;     // [64 k][64 d]
    float* Ps = sm + 12288;    // [64 q][68]

    const int tid = threadIdx.x;
    const int tx = tid & 15, ty = tid >> 4;
    const int qt = blockIdx.x;
    const int nh = blockIdx.y;
    const int q0 = qt * 64;

    const float* Qg = g_q + (size_t)nh * LQ * DD;
    const float* Kg = g_k + (size_t)nh * LQ * DD;
    const float* Vg = g_v + (size_t)nh * LQ * DD;

    // Q tile: load transposed, scale by 1/sqrt(D)=0.125 (exact)
#pragma unroll
    for (int it = 0; it < 4; it++) {
        int idx = tid + it * 256;
        int row = idx >> 4, d4 = (idx & 15) << 2;
        float4 v = *(const float4*)(Qg + (size_t)(q0 + row) * DD + d4);
        Qt[(d4 + 0) * 64 + row] = v.x * 0.125f;
        Qt[(d4 + 1) * 64 + row] = v.y * 0.125f;
        Qt[(d4 + 2) * 64 + row] = v.z * 0.125f;
        Qt[(d4 + 3) * 64 + row] = v.w * 0.125f;
    }

    float O[4][4], m[4], lsum[4];
#pragma unroll
    for (int i = 0; i < 4; i++) {
        m[i] = -1e30f; lsum[i] = 0.f;
#pragma unroll
        for (int j = 0; j < 4; j++) O[i][j] = 0.f;
    }

    for (int jt = 0; jt <= qt; jt++) {
        const int k0 = jt * 64;
        __syncthreads();  // prev PV done (also orders Qt load on first iter)
#pragma unroll
        for (int it = 0; it < 4; it++) {
            int idx = tid + it * 256;
            int row = idx >> 4, d4 = (idx & 15) << 2;
            float4 v = *(const float4*)(Kg + (size_t)(k0 + row) * DD + d4);
            Kt[(d4 + 0) * 64 + row] = v.x; Kt[(d4 + 1) * 64 + row] = v.y;
            Kt[(d4 + 2) * 64 + row] = v.z; Kt[(d4 + 3) * 64 + row] = v.w;
            float4 w = *(const float4*)(Vg + (size_t)(k0 + row) * DD + d4);
            *(float4*)(Vs + row * 64 + d4) = w;
        }
        __syncthreads();

        // S = (Q/8) @ K^T, 4x4 per thread
        float s[4][4];
#pragma unroll
        for (int i = 0; i < 4; i++)
#pragma unroll
            for (int j = 0; j < 4; j++) s[i][j] = 0.f;
#pragma unroll 16
        for (int d = 0; d < 64; d++) {
            float4 qa = *(const float4*)&Qt[d * 64 + ty * 4];
            float4 kb = *(const float4*)&Kt[d * 64 + tx * 4];
            float qv[4] = {qa.x, qa.y, qa.z, qa.w};
            float kv[4] = {kb.x, kb.y, kb.z, kb.w};
#pragma unroll
            for (int i = 0; i < 4; i++)
#pragma unroll
                for (int j = 0; j < 4; j++)
                    s[i][j] = fmaf(qv[i], kv[j], s[i][j]);
        }

        if (jt == qt) {  // causal mask on diagonal tile only
#pragma unroll
            for (int i = 0; i < 4; i++)
#pragma unroll
                for (int j = 0; j < 4; j++)
                    if (k0 + tx * 4 + j > q0 + ty * 4 + i) s[i][j] = -1e30f;
        }

        // online softmax (row groups = 16 lanes sharing ty)
#pragma unroll
        for (int i = 0; i < 4; i++) {
            float mloc = fmaxf(fmaxf(s[i][0], s[i][1]), fmaxf(s[i][2], s[i][3]));
            mloc = rmax16(mloc);
            float mnew = fmaxf(m[i], mloc);
            float alpha = __expf(m[i] - mnew);
            float p0 = __expf(s[i][0] - mnew);
            float p1 = __expf(s[i][1] - mnew);
            float p2 = __expf(s[i][2] - mnew);
            float p3 = __expf(s[i][3] - mnew);
            float lloc = rsum16(p0 + p1 + p2 + p3);
            lsum[i] = lsum[i] * alpha + lloc;
            m[i] = mnew;
#pragma unroll
            for (int j = 0; j < 4; j++) O[i][j] *= alpha;
            *(float4*)&Ps[(ty * 4 + i) * PSTRIDE + tx * 4] = make_float4(p0, p1, p2, p3);
        }
        __syncthreads();

        // O += P @ V
#pragma unroll 4
        for (int k = 0; k < 64; k += 4) {
            float4 a[4], b[4];
#pragma unroll
            for (int i = 0; i < 4; i++) a[i] = *(const float4*)&Ps[(ty * 4 + i) * PSTRIDE + k];
#pragma unroll
            for (int kk = 0; kk < 4; kk++) b[kk] = *(const float4*)&Vs[(k + kk) * 64 + tx * 4];
#pragma unroll
            for (int i = 0; i < 4; i++) {
                float av[4] = {a[i].x, a[i].y, a[i].z, a[i].w};
#pragma unroll
                for (int kk = 0; kk < 4; kk++) {
                    float bv[4] = {b[kk].x, b[kk].y, b[kk].z, b[kk].w};
#pragma unroll
                    for (int j = 0; j < 4; j++)
                        O[i][j] = fmaf(av[kk], bv[j], O[i][j]);
                }
            }
        }
    }

    // normalize + store to (N, L, E) layout for the output projection
    const int n = nh / HH, h = nh % HH;
#pragma unroll
    for (int i = 0; i < 4; i++) {
        float inv = 1.f / lsum[i];
        int q = q0 + ty * 4 + i;
        float4 v = make_float4(O[i][0] * inv, O[i][1] * inv, O[i][2] * inv, O[i][3] * inv);
        *(float4*)(g_att + ((size_t)(n * LQ + q)) * EE + h * DD + tx * 4) = v;
    }
}

// ---------------------------------------------------------------------------
extern "C" void kernel_launch(void* const* d_in, const int* in_sizes, int n_in,
                              void* d_out, int out_size)
{
    (void)in_sizes; (void)n_in; (void)out_size;
    const float* q  = (const float*)d_in[0];
    const float* k  = (const float*)d_in[1];
    const float* v  = (const float*)d_in[2];
    const float* wq = (const float*)d_in[3];
    const float* wk = (const float*)d_in[4];
    const float* wv = (const float*)d_in[5];
    const float* wo = (const float*)d_in[6];
    // d_in[7] = mask: causal tril per reference; handled analytically.
    float* out = (float*)d_out;

    float *pq, *pk, *pv, *patt;
    cudaGetSymbolAddress((void**)&pq,   g_q);
    cudaGetSymbolAddress((void**)&pk,   g_k);
    cudaGetSymbolAddress((void**)&pv,   g_v);
    cudaGetSymbolAddress((void**)&patt, g_att);

    cudaFuncSetAttribute(flash_kernel, cudaFuncAttributeMaxDynamicSharedMemorySize,
                         SMEM_FLASH);

    dim3 gg(EE / 128, NL / 128);
    gemm_nt<<<gg, 256>>>(q, wq, pq, 1);
    gemm_nt<<<gg, 256>>>(k, wk, pk, 1);
    gemm_nt<<<gg, 256>>>(v, wv, pv, 1);

    flash_kernel<<<dim3(LQ / 64, NB * HH), 256, SMEM_FLASH>>>();

    gemm_nt<<<gg, 256>>>(patt, wo, out, 0);
}

// round 3
// speedup vs baseline: 1.4420x; 1.4420x over previous
#include <cuda_runtime.h>
#include <cuda_bf16.h>
#include <cstdint>
#include <math.h>

#define NB 4
#define LQ 2048
#define EE 1024
#define HH 16
#define DD 64
#define NL (NB*LQ)   /* 8192 */
#define GK EE        /* 1024 */

// ---------------------------------------------------------------------------
// Scratch (allocation-free rule: __device__ globals)
// ---------------------------------------------------------------------------
__device__ float g_q[(size_t)NB*HH*LQ*DD];
__device__ float g_k[(size_t)NB*HH*LQ*DD];
__device__ float g_v[(size_t)NB*HH*LQ*DD];
__device__ float g_att[(size_t)NB*LQ*EE];

__device__ __nv_bfloat16 g_xhi[(size_t)3*NL*GK];   // q,k,v inputs hi
__device__ __nv_bfloat16 g_xlo[(size_t)3*NL*GK];
__device__ __nv_bfloat16 g_whi[(size_t)4*GK*GK];   // wq,wk,wv,wo hi
__device__ __nv_bfloat16 g_wlo[(size_t)4*GK*GK];
__device__ __nv_bfloat16 g_ahi[(size_t)NL*GK];     // attention output hi
__device__ __nv_bfloat16 g_alo[(size_t)NL*GK];

// ---------------------------------------------------------------------------
// Split fp32 -> bf16 hi/lo
// ---------------------------------------------------------------------------
__global__ void split_kernel(const float* __restrict__ x,
                             __nv_bfloat16* __restrict__ hi,
                             __nv_bfloat16* __restrict__ lo, int n4) {
    int i = blockIdx.x * blockDim.x + threadIdx.x;
    if (i >= n4) return;
    float4 v = ((const float4*)x)[i];
    float f[4] = {v.x, v.y, v.z, v.w};
    __nv_bfloat16 h[4], l[4];
#pragma unroll
    for (int j = 0; j < 4; j++) {
        h[j] = __float2bfloat16(f[j]);
        l[j] = __float2bfloat16(f[j] - __bfloat162float(h[j]));
    }
    *(uint2*)(hi + (size_t)4 * i) = *(const uint2*)h;
    *(uint2*)(lo + (size_t)4 * i) = *(const uint2*)l;
}

// ---------------------------------------------------------------------------
// bf16 mma.sync GEMM: C[8192,1024] = A @ B^T, 3-product hi/lo split.
// Tile 128x128, BK=32 bf16, 256 threads (8 warps of 64x32), cp.async double buf.
// Swizzle: line = row>>1 (128B), slot = ((row&1)<<2 | kc) ^ (line&7), kc = 16B chunk.
// ---------------------------------------------------------------------------
__device__ __forceinline__ uint32_t swz(int row, int kc) {
    int line = row >> 1;
    int slot = (((row & 1) << 2) | kc) ^ (line & 7);
    return (uint32_t)(line * 128 + slot * 16);
}
__device__ __forceinline__ void cp16(uint32_t smem, const void* g) {
    asm volatile("cp.async.cg.shared.global [%0], [%1], 16;" :: "r"(smem), "l"(g));
}
#define CP_COMMIT() asm volatile("cp.async.commit_group;" ::: "memory")

__device__ __forceinline__ void ldm_x4(uint32_t* r, uint32_t addr) {
    asm volatile("ldmatrix.sync.aligned.m8n8.x4.shared.b16 {%0,%1,%2,%3}, [%4];"
                 : "=r"(r[0]), "=r"(r[1]), "=r"(r[2]), "=r"(r[3]) : "r"(addr));
}
__device__ __forceinline__ void mma16816(float* d, const uint32_t* a, const uint32_t* b) {
    asm volatile("mma.sync.aligned.m16n8k16.row.col.f32.bf16.bf16.f32 "
                 "{%0,%1,%2,%3}, {%4,%5,%6,%7}, {%8,%9}, {%0,%1,%2,%3};"
                 : "+f"(d[0]), "+f"(d[1]), "+f"(d[2]), "+f"(d[3])
                 : "r"(a[0]), "r"(a[1]), "r"(a[2]), "r"(a[3]), "r"(b[0]), "r"(b[1]));
}

#define NITER 96   /* 3 passes * 32 k-tiles */

__global__ __launch_bounds__(256)
void gemm_mma(const __nv_bfloat16* __restrict__ Ah, const __nv_bfloat16* __restrict__ Al,
              const __nv_bfloat16* __restrict__ Bh, const __nv_bfloat16* __restrict__ Bl,
              float* __restrict__ C, int head_major)
{
    __shared__ __nv_bfloat16 As[2][128 * 32];
    __shared__ __nv_bfloat16 Bs[2][128 * 32];

    const int tid = threadIdx.x;
    const int wid = tid >> 5, lane = tid & 31;
    const int wm = wid & 1, wn = wid >> 1;          // warp tile origin
    const int m0 = wm * 64, n0 = wn * 32;
    const int row0 = blockIdx.y * 128, col0 = blockIdx.x * 128;

    const uint32_t sA[2] = {(uint32_t)__cvta_generic_to_shared(&As[0][0]),
                            (uint32_t)__cvta_generic_to_shared(&As[1][0])};
    const uint32_t sB[2] = {(uint32_t)__cvta_generic_to_shared(&Bs[0][0]),
                            (uint32_t)__cvta_generic_to_shared(&Bs[1][0])};

    const __nv_bfloat16* Ap[3] = {Ah, Ah, Al};
    const __nv_bfloat16* Bp[3] = {Bh, Bl, Bh};

    float acc[4][4][4];
#pragma unroll
    for (int t = 0; t < 4; t++)
#pragma unroll
        for (int u = 0; u < 4; u++)
#pragma unroll
            for (int e = 0; e < 4; e++) acc[t][u][e] = 0.f;

    // per-thread load slots: chunks c = tid, tid+256; row=c>>2, kc=c&3
    auto load_tile = [&](int it, int b) {
        const __nv_bfloat16* Abase = Ap[it >> 5];
        const __nv_bfloat16* Bbase = Bp[it >> 5];
        const int kt = (it & 31) << 5;
#pragma unroll
        for (int j = 0; j < 2; j++) {
            int c = tid + j * 256;
            int row = c >> 2, kc = c & 3;
            uint32_t so = swz(row, kc);
            cp16(sA[b] + so, Abase + (size_t)(row0 + row) * GK + kt + kc * 8);
            cp16(sB[b] + so, Bbase + (size_t)(col0 + row) * GK + kt + kc * 8);
        }
    };

    load_tile(0, 0); CP_COMMIT();
    load_tile(1, 1); CP_COMMIT();

    // precomputed ldmatrix intra-tile offsets (lane-dependent)
    const int a_row = lane & 15;            // + m0 + t*16
    const int a_kc  = lane >> 4;            // + 2s
    const int b_row = lane & 7;             // + n0 + (u2*2 + (lane>>4))*8
    const int b_sel = (lane >> 4) & 1;
    const int b_kc  = (lane >> 3) & 1;      // + 2s

    for (int it = 0; it < NITER; it++) {
        const int b = it & 1;
        asm volatile("cp.async.wait_group 1;" ::: "memory");
        __syncthreads();

#pragma unroll
        for (int s = 0; s < 2; s++) {
            uint32_t af[4][4], bf[4][2];
#pragma unroll
            for (int t = 0; t < 4; t++) {
                int r = m0 + t * 16 + a_row;
                ldm_x4(af[t], sA[b] + swz(r, 2 * s + a_kc));
            }
#pragma unroll
            for (int u2 = 0; u2 < 2; u2++) {
                uint32_t r4[4];
                int r = n0 + (u2 * 2 + b_sel) * 8 + b_row;
                ldm_x4(r4, sB[b] + swz(r, 2 * s + b_kc));
                bf[u2*2][0] = r4[0]; bf[u2*2][1] = r4[1];
                bf[u2*2+1][0] = r4[2]; bf[u2*2+1][1] = r4[3];
            }
#pragma unroll
            for (int t = 0; t < 4; t++)
#pragma unroll
                for (int u = 0; u < 4; u++)
                    mma16816(acc[t][u], af[t], bf[u]);
        }

        __syncthreads();
        if (it + 2 < NITER) load_tile(it + 2, b);
        CP_COMMIT();
    }

    // epilogue: acc layout m16n8 -> rows l/4, l/4+8; cols (l%4)*2, +1
    const int er = lane >> 2, ec = (lane & 3) * 2;
#pragma unroll
    for (int t = 0; t < 4; t++) {
#pragma unroll
        for (int u = 0; u < 4; u++) {
            int col = col0 + n0 + u * 8 + ec;
#pragma unroll
            for (int half = 0; half < 2; half++) {
                int row = row0 + m0 + t * 16 + er + half * 8;
                float2 v = make_float2(acc[t][u][half*2], acc[t][u][half*2+1]);
                if (head_major) {
                    int n = row >> 11, l = row & 2047;
                    int h = col >> 6, d = col & 63;
                    *(float2*)(C + ((size_t)((n * HH + h) * LQ + l)) * DD + d) = v;
                } else {
                    *(float2*)(C + (size_t)row * EE + col) = v;
                }
            }
        }
    }
}

// ---------------------------------------------------------------------------
// Flash attention, fp32 (unchanged from R1 — proven at 1.36ms).
// ---------------------------------------------------------------------------
__device__ __forceinline__ float rmax16(float v) {
#pragma unroll
    for (int o = 8; o > 0; o >>= 1) v = fmaxf(v, __shfl_xor_sync(0xffffffffu, v, o, 16));
    return v;
}
__device__ __forceinline__ float rsum16(float v) {
#pragma unroll
    for (int o = 8; o > 0; o >>= 1) v += __shfl_xor_sync(0xffffffffu, v, o, 16);
    return v;
}

#define PSTRIDE 68
#define SMEM_FLASH ((3 * 4096 + 64 * PSTRIDE) * (int)sizeof(float))

__global__ void flash_kernel()
{
    extern __shared__ float smf[];
    float* Qt = smf;
    float* Kt = smf + 4096;
    float* Vs = smf + 8192;
    float* Ps = smf + 12288;

    const int tid = threadIdx.x;
    const int tx = tid & 15, ty = tid >> 4;
    const int qt = blockIdx.x;
    const int nh = blockIdx.y;
    const int q0 = qt * 64;

    const float* Qg = g_q + (size_t)nh * LQ * DD;
    const float* Kg = g_k + (size_t)nh * LQ * DD;
    const float* Vg = g_v + (size_t)nh * LQ * DD;

#pragma unroll
    for (int it = 0; it < 4; it++) {
        int idx = tid + it * 256;
        int row = idx >> 4, d4 = (idx & 15) << 2;
        float4 v = *(const float4*)(Qg + (size_t)(q0 + row) * DD + d4);
        Qt[(d4 + 0) * 64 + row] = v.x * 0.125f;
        Qt[(d4 + 1) * 64 + row] = v.y * 0.125f;
        Qt[(d4 + 2) * 64 + row] = v.z * 0.125f;
        Qt[(d4 + 3) * 64 + row] = v.w * 0.125f;
    }

    float O[4][4], m[4], lsum[4];
#pragma unroll
    for (int i = 0; i < 4; i++) {
        m[i] = -1e30f; lsum[i] = 0.f;
#pragma unroll
        for (int j = 0; j < 4; j++) O[i][j] = 0.f;
    }

    for (int jt = 0; jt <= qt; jt++) {
        const int k0 = jt * 64;
        __syncthreads();
#pragma unroll
        for (int it = 0; it < 4; it++) {
            int idx = tid + it * 256;
            int row = idx >> 4, d4 = (idx & 15) << 2;
            float4 v = *(const float4*)(Kg + (size_t)(k0 + row) * DD + d4);
            Kt[(d4 + 0) * 64 + row] = v.x; Kt[(d4 + 1) * 64 + row] = v.y;
            Kt[(d4 + 2) * 64 + row] = v.z; Kt[(d4 + 3) * 64 + row] = v.w;
            float4 w = *(const float4*)(Vg + (size_t)(k0 + row) * DD + d4);
            *(float4*)(Vs + row * 64 + d4) = w;
        }
        __syncthreads();

        float s[4][4];
#pragma unroll
        for (int i = 0; i < 4; i++)
#pragma unroll
            for (int j = 0; j < 4; j++) s[i][j] = 0.f;
#pragma unroll 16
        for (int d = 0; d < 64; d++) {
            float4 qa = *(const float4*)&Qt[d * 64 + ty * 4];
            float4 kb = *(const float4*)&Kt[d * 64 + tx * 4];
            float qv[4] = {qa.x, qa.y, qa.z, qa.w};
            float kv[4] = {kb.x, kb.y, kb.z, kb.w};
#pragma unroll
            for (int i = 0; i < 4; i++)
#pragma unroll
                for (int j = 0; j < 4; j++)
                    s[i][j] = fmaf(qv[i], kv[j], s[i][j]);
        }

        if (jt == qt) {
#pragma unroll
            for (int i = 0; i < 4; i++)
#pragma unroll
                for (int j = 0; j < 4; j++)
                    if (k0 + tx * 4 + j > q0 + ty * 4 + i) s[i][j] = -1e30f;
        }

#pragma unroll
        for (int i = 0; i < 4; i++) {
            float mloc = fmaxf(fmaxf(s[i][0], s[i][1]), fmaxf(s[i][2], s[i][3]));
            mloc = rmax16(mloc);
            float mnew = fmaxf(m[i], mloc);
            float alpha = __expf(m[i] - mnew);
            float p0 = __expf(s[i][0] - mnew);
            float p1 = __expf(s[i][1] - mnew);
            float p2 = __expf(s[i][2] - mnew);
            float p3 = __expf(s[i][3] - mnew);
            float lloc = rsum16(p0 + p1 + p2 + p3);
            lsum[i] = lsum[i] * alpha + lloc;
            m[i] = mnew;
#pragma unroll
            for (int j = 0; j < 4; j++) O[i][j] *= alpha;
            *(float4*)&Ps[(ty * 4 + i) * PSTRIDE + tx * 4] = make_float4(p0, p1, p2, p3);
        }
        __syncthreads();

#pragma unroll 4
        for (int k = 0; k < 64; k += 4) {
            float4 a[4], b[4];
#pragma unroll
            for (int i = 0; i < 4; i++) a[i] = *(const float4*)&Ps[(ty * 4 + i) * PSTRIDE + k];
#pragma unroll
            for (int kk = 0; kk < 4; kk++) b[kk] = *(const float4*)&Vs[(k + kk) * 64 + tx * 4];
#pragma unroll
            for (int i = 0; i < 4; i++) {
                float av[4] = {a[i].x, a[i].y, a[i].z, a[i].w};
#pragma unroll
                for (int kk = 0; kk < 4; kk++) {
                    float bv[4] = {b[kk].x, b[kk].y, b[kk].z, b[kk].w};
#pragma unroll
                    for (int j = 0; j < 4; j++)
                        O[i][j] = fmaf(av[kk], bv[j], O[i][j]);
                }
            }
        }
    }

    const int n = nh / HH, h = nh % HH;
#pragma unroll
    for (int i = 0; i < 4; i++) {
        float inv = 1.f / lsum[i];
        int q = q0 + ty * 4 + i;
        float4 v = make_float4(O[i][0] * inv, O[i][1] * inv, O[i][2] * inv, O[i][3] * inv);
        *(float4*)(g_att + ((size_t)(n * LQ + q)) * EE + h * DD + tx * 4) = v;
    }
}

// ---------------------------------------------------------------------------
extern "C" void kernel_launch(void* const* d_in, const int* in_sizes, int n_in,
                              void* d_out, int out_size)
{
    (void)in_sizes; (void)n_in; (void)out_size;
    const float* q  = (const float*)d_in[0];
    const float* k  = (const float*)d_in[1];
    const float* v  = (const float*)d_in[2];
    const float* wq = (const float*)d_in[3];
    const float* wk = (const float*)d_in[4];
    const float* wv = (const float*)d_in[5];
    const float* wo = (const float*)d_in[6];
    float* out = (float*)d_out;

    float *pq, *pk, *pv, *patt;
    __nv_bfloat16 *xhi, *xlo, *whi, *wlo, *ahi, *alo;
    cudaGetSymbolAddress((void**)&pq,   g_q);
    cudaGetSymbolAddress((void**)&pk,   g_k);
    cudaGetSymbolAddress((void**)&pv,   g_v);
    cudaGetSymbolAddress((void**)&patt, g_att);
    cudaGetSymbolAddress((void**)&xhi,  g_xhi);
    cudaGetSymbolAddress((void**)&xlo,  g_xlo);
    cudaGetSymbolAddress((void**)&whi,  g_whi);
    cudaGetSymbolAddress((void**)&wlo,  g_wlo);
    cudaGetSymbolAddress((void**)&ahi,  g_ahi);
    cudaGetSymbolAddress((void**)&alo,  g_alo);

    cudaFuncSetAttribute(flash_kernel, cudaFuncAttributeMaxDynamicSharedMemorySize,
                         SMEM_FLASH);

    const size_t NX = (size_t)NL * GK;
    const size_t NW = (size_t)GK * GK;
    const int TB = 256;
    split_kernel<<<(int)(NX/4 + TB - 1)/TB, TB>>>(q,  xhi,          xlo,          (int)(NX/4));
    split_kernel<<<(int)(NX/4 + TB - 1)/TB, TB>>>(k,  xhi + NX,     xlo + NX,     (int)(NX/4));
    split_kernel<<<(int)(NX/4 + TB - 1)/TB, TB>>>(v,  xhi + 2*NX,   xlo + 2*NX,   (int)(NX/4));
    split_kernel<<<(int)(NW/4 + TB - 1)/TB, TB>>>(wq, whi,          wlo,          (int)(NW/4));
    split_kernel<<<(int)(NW/4 + TB - 1)/TB, TB>>>(wk, whi + NW,     wlo + NW,     (int)(NW/4));
    split_kernel<<<(int)(NW/4 + TB - 1)/TB, TB>>>(wv, whi + 2*NW,   wlo + 2*NW,   (int)(NW/4));
    split_kernel<<<(int)(NW/4 + TB - 1)/TB, TB>>>(wo, whi + 3*NW,   wlo + 3*NW,   (int)(NW/4));

    dim3 gg(EE / 128, NL / 128);
    gemm_mma<<<gg, 256>>>(xhi,        xlo,        whi,        wlo,        pq, 1);
    gemm_mma<<<gg, 256>>>(xhi + NX,   xlo + NX,   whi + NW,   wlo + NW,   pk, 1);
    gemm_mma<<<gg, 256>>>(xhi + 2*NX, xlo + 2*NX, whi + 2*NW, wlo + 2*NW, pv, 1);

    flash_kernel<<<dim3(LQ / 64, NB * HH), 256, SMEM_FLASH>>>();

    split_kernel<<<(int)(NX/4 + TB - 1)/TB, TB>>>(patt, ahi, alo, (int)(NX/4));
    gemm_mma<<<gg, 256>>>(ahi, alo, whi + 3*NW, wlo + 3*NW, out, 0);
}

// round 6
// speedup vs baseline: 3.0058x; 2.0845x over previous
#include <cuda_runtime.h>
#include <cuda_bf16.h>
#include <cuda_fp16.h>
#include <cstdint>
#include <math.h>

#define NB 4
#define LQ 2048
#define EE 1024
#define HH 16
#define DD 64
#define NL (NB*LQ)   /* 8192 */
#define GK EE        /* 1024 */

// log2(e)/sqrt(64): folded into Q so softmax uses exp2
#define QSCALE 0.18033688011112042f

// ---------------------------------------------------------------------------
// Scratch (allocation-free rule: __device__ globals)
// ---------------------------------------------------------------------------
__device__ __nv_bfloat16 g_xhi[(size_t)3*NL*GK];   // q,k,v inputs hi (bf16, GEMM A)
__device__ __nv_bfloat16 g_xlo[(size_t)3*NL*GK];
__device__ __nv_bfloat16 g_whi[(size_t)4*GK*GK];   // wq,wk,wv,wo hi
__device__ __nv_bfloat16 g_wlo[(size_t)4*GK*GK];
__device__ __half g_qh[(size_t)NL*GK];             // head-major fp16 hi/lo
__device__ __half g_ql[(size_t)NL*GK];
__device__ __half g_kh[(size_t)NL*GK];
__device__ __half g_kl[(size_t)NL*GK];
__device__ __half g_vh[(size_t)NL*GK];
__device__ __half g_vl[(size_t)NL*GK];
__device__ __nv_bfloat16 g_ahi[(size_t)NL*GK];     // attention out hi/lo (bf16)
__device__ __nv_bfloat16 g_alo[(size_t)NL*GK];

// ---------------------------------------------------------------------------
// common PTX helpers
// ---------------------------------------------------------------------------
__device__ __forceinline__ void cp16(uint32_t smem, const void* g) {
    asm volatile("cp.async.cg.shared.global [%0], [%1], 16;" :: "r"(smem), "l"(g));
}
#define CP_COMMIT() asm volatile("cp.async.commit_group;" ::: "memory")
#define CP_WAIT(n)  asm volatile("cp.async.wait_group %0;" :: "n"(n) : "memory")

__device__ __forceinline__ void ldm_x4(uint32_t* r, uint32_t addr) {
    asm volatile("ldmatrix.sync.aligned.m8n8.x4.shared.b16 {%0,%1,%2,%3}, [%4];"
                 : "=r"(r[0]), "=r"(r[1]), "=r"(r[2]), "=r"(r[3]) : "r"(addr));
}
__device__ __forceinline__ void ldm_x4t(uint32_t* r, uint32_t addr) {
    asm volatile("ldmatrix.sync.aligned.m8n8.x4.trans.shared.b16 {%0,%1,%2,%3}, [%4];"
                 : "=r"(r[0]), "=r"(r[1]), "=r"(r[2]), "=r"(r[3]) : "r"(addr));
}
__device__ __forceinline__ void mma_bf16(float* d, const uint32_t* a, const uint32_t* b) {
    asm volatile("mma.sync.aligned.m16n8k16.row.col.f32.bf16.bf16.f32 "
                 "{%0,%1,%2,%3}, {%4,%5,%6,%7}, {%8,%9}, {%0,%1,%2,%3};"
                 : "+f"(d[0]), "+f"(d[1]), "+f"(d[2]), "+f"(d[3])
                 : "r"(a[0]), "r"(a[1]), "r"(a[2]), "r"(a[3]), "r"(b[0]), "r"(b[1]));
}
__device__ __forceinline__ void mma_f16(float* d, const uint32_t* a, const uint32_t* b) {
    asm volatile("mma.sync.aligned.m16n8k16.row.col.f32.f16.f16.f32 "
                 "{%0,%1,%2,%3}, {%4,%5,%6,%7}, {%8,%9}, {%0,%1,%2,%3};"
                 : "+f"(d[0]), "+f"(d[1]), "+f"(d[2]), "+f"(d[3])
                 : "r"(a[0]), "r"(a[1]), "r"(a[2]), "r"(a[3]), "r"(b[0]), "r"(b[1]));
}
__device__ __forceinline__ uint32_t packh2(float lo, float hi) {
    uint32_t r;
    asm("cvt.rn.f16x2.f32 %0, %1, %2;" : "=r"(r) : "f"(hi), "f"(lo));
    return r;
}

// ---------------------------------------------------------------------------
// Split fp32 -> bf16 hi/lo
// ---------------------------------------------------------------------------
__global__ void split_kernel(const float* __restrict__ x,
                             __nv_bfloat16* __restrict__ hi,
                             __nv_bfloat16* __restrict__ lo, int n4) {
    int i = blockIdx.x * blockDim.x + threadIdx.x;
    if (i >= n4) return;
    float4 v = ((const float4*)x)[i];
    float f[4] = {v.x, v.y, v.z, v.w};
    __nv_bfloat16 h[4], l[4];
#pragma unroll
    for (int j = 0; j < 4; j++) {
        h[j] = __float2bfloat16(f[j]);
        l[j] = __float2bfloat16(f[j] - __bfloat162float(h[j]));
    }
    *(uint2*)(hi + (size_t)4 * i) = *(const uint2*)h;
    *(uint2*)(lo + (size_t)4 * i) = *(const uint2*)l;
}

// ---------------------------------------------------------------------------
// bf16 mma.sync GEMM: C[8192,1024] = A @ B^T, 3-product hi/lo split.
// Tile 128x128, BK=32, 256 threads, 4-stage cp.async pipeline.
// mode 0: fp32 C[row][EE].  mode 1: fp16 hi/lo head-major [(n*HH+h)*LQ+l][d], *scale.
// ---------------------------------------------------------------------------
__device__ __forceinline__ uint32_t swzg(int row, int kc) {  // 64B rows, 2/line
    int line = row >> 1;
    int slot = (((row & 1) << 2) | kc) ^ (line & 7);
    return (uint32_t)(line * 128 + slot * 16);
}

#define NITER 96   /* 3 passes * 32 k-tiles */
#define GEMM_SMEM (4 * 16384)

__global__ __launch_bounds__(256)
void gemm_mma(const __nv_bfloat16* __restrict__ Ah, const __nv_bfloat16* __restrict__ Al,
              const __nv_bfloat16* __restrict__ Bh, const __nv_bfloat16* __restrict__ Bl,
              float* __restrict__ C, __half* __restrict__ Chi, __half* __restrict__ Clo,
              int mode, float scale)
{
    extern __shared__ char smg[];
    const uint32_t sb = (uint32_t)__cvta_generic_to_shared(smg);

    const int tid = threadIdx.x;
    const int wid = tid >> 5, lane = tid & 31;
    const int wm = wid & 1, wn = wid >> 1;
    const int m0 = wm * 64, n0 = wn * 32;
    const int row0 = blockIdx.y * 128, col0 = blockIdx.x * 128;

    const __nv_bfloat16* Ap[3] = {Ah, Ah, Al};
    const __nv_bfloat16* Bp[3] = {Bh, Bl, Bh};

    float acc[4][4][4];
#pragma unroll
    for (int t = 0; t < 4; t++)
#pragma unroll
        for (int u = 0; u < 4; u++)
#pragma unroll
            for (int e = 0; e < 4; e++) acc[t][u][e] = 0.f;

    auto load_tile = [&](int it, int s) {
        const __nv_bfloat16* Abase = Ap[it >> 5];
        const __nv_bfloat16* Bbase = Bp[it >> 5];
        const int kt = (it & 31) << 5;
        const uint32_t sA = sb + s * 16384, sB = sA + 8192;
#pragma unroll
        for (int j = 0; j < 2; j++) {
            int c = tid + j * 256;
            int row = c >> 2, kc = c & 3;
            uint32_t so = swzg(row, kc);
            cp16(sA + so, Abase + (size_t)(row0 + row) * GK + kt + kc * 8);
            cp16(sB + so, Bbase + (size_t)(col0 + row) * GK + kt + kc * 8);
        }
    };

    load_tile(0, 0); CP_COMMIT();
    load_tile(1, 1); CP_COMMIT();
    load_tile(2, 2); CP_COMMIT();

    const int a_row = lane & 15;
    const int a_kc  = lane >> 4;
    const int b_row = lane & 7;
    const int b_sel = (lane >> 4) & 1;
    const int b_kc  = (lane >> 3) & 1;

    for (int it = 0; it < NITER; it++) {
        const int bu = it & 3;
        const uint32_t sA = sb + bu * 16384, sB = sA + 8192;
        CP_WAIT(2);
        __syncthreads();

#pragma unroll
        for (int s = 0; s < 2; s++) {
            uint32_t af[4][4], bf[4][2];
#pragma unroll
            for (int t = 0; t < 4; t++)
                ldm_x4(af[t], sA + swzg(m0 + t * 16 + a_row, 2 * s + a_kc));
#pragma unroll
            for (int u2 = 0; u2 < 2; u2++) {
                uint32_t r4[4];
                ldm_x4(r4, sB + swzg(n0 + (u2 * 2 + b_sel) * 8 + b_row, 2 * s + b_kc));
                bf[u2*2][0] = r4[0]; bf[u2*2][1] = r4[1];
                bf[u2*2+1][0] = r4[2]; bf[u2*2+1][1] = r4[3];
            }
#pragma unroll
            for (int t = 0; t < 4; t++)
#pragma unroll
                for (int u = 0; u < 4; u++)
                    mma_bf16(acc[t][u], af[t], bf[u]);
        }

        if (it + 3 < NITER) load_tile(it + 3, (it + 3) & 3);
        CP_COMMIT();
    }

    const int er = lane >> 2, ec = (lane & 3) * 2;
#pragma unroll
    for (int t = 0; t < 4; t++) {
#pragma unroll
        for (int u = 0; u < 4; u++) {
            int col = col0 + n0 + u * 8 + ec;
#pragma unroll
            for (int half_ = 0; half_ < 2; half_++) {
                int row = row0 + m0 + t * 16 + er + half_ * 8;
                float x = acc[t][u][half_*2] * scale, y = acc[t][u][half_*2+1] * scale;
                if (mode == 0) {
                    *(float2*)(C + (size_t)row * EE + col) = make_float2(x, y);
                } else {
                    int n = row >> 11, l = row & 2047;
                    int hh = col >> 6, d = col & 63;
                    size_t off = ((size_t)((n * HH + hh) * LQ + l)) * DD + d;
                    __half hx = __float2half_rn(x), hy = __float2half_rn(y);
                    __half lx = __float2half_rn(x - __half2float(hx));
                    __half ly = __float2half_rn(y - __half2float(hy));
                    __half hp[2] = {hx, hy}, lp[2] = {lx, ly};
                    *(uint32_t*)(Chi + off) = *(const uint32_t*)hp;
                    *(uint32_t*)(Clo + off) = *(const uint32_t*)lp;
                }
            }
        }
    }
}

// ---------------------------------------------------------------------------
// Flash attention with mma.sync fp16, hi/lo split QK^T and PV.
// Block = 128 q rows x one (n,h). 8 warps x 16 q rows. k-tiles of 64, 4-stage.
// smem bytes: Qh 0, Ql 16K, stage s at 32K+s*32K: {Kh, Kl, Vh, Vl} x 8K.
// ---------------------------------------------------------------------------
__device__ __forceinline__ uint32_t swzf(int row, int ch) {  // 128B rows
    return (uint32_t)(row * 128 + ((ch ^ (row & 7)) << 4));
}
#define FLASH_SMEM (32768 + 4 * 32768)

__global__ __launch_bounds__(256)
void flash_mma()
{
    extern __shared__ char smf[];
    const uint32_t sb = (uint32_t)__cvta_generic_to_shared(smf);
    const int tid = threadIdx.x;
    const int wid = tid >> 5, lane = tid & 31;
    const int qb = 15 - (int)blockIdx.x;      // heavy blocks first
    const int nh = blockIdx.y;
    const int q0 = qb * 128;
    const int nkt = 2 * (qb + 1);

    const size_t hb = (size_t)nh * LQ * DD;
    const __half* Qhg = g_qh + hb; const __half* Qlg = g_ql + hb;
    const __half* Khg = g_kh + hb; const __half* Klg = g_kl + hb;
    const __half* Vhg = g_vh + hb; const __half* Vlg = g_vl + hb;

    // Q (hi+lo): 2048 16B chunks
#pragma unroll
    for (int j = 0; j < 8; j++) {
        int c = tid + j * 256;
        int tsr = c >> 10, cc = c & 1023, row = cc >> 3, ch = cc & 7;
        const __half* src = tsr ? Qlg : Qhg;
        cp16(sb + tsr * 16384 + swzf(row, ch), src + (size_t)(q0 + row) * DD + ch * 8);
    }
    CP_COMMIT();

    auto load_kv = [&](int jt, int s) {
        const int k0 = jt * 64;
        const uint32_t stb = sb + 32768 + s * 32768;
#pragma unroll
        for (int j = 0; j < 8; j++) {
            int c = tid + j * 256;
            int tsr = c >> 9, cc = c & 511, row = cc >> 3, ch = cc & 7;
            const __half* src = (tsr == 0) ? Khg : (tsr == 1) ? Klg : (tsr == 2) ? Vhg : Vlg;
            cp16(stb + tsr * 8192 + swzf(row, ch), src + (size_t)(k0 + row) * DD + ch * 8);
        }
    };
    load_kv(0, 0); CP_COMMIT();
    if (nkt > 1) load_kv(1, 1);
    CP_COMMIT();
    if (nkt > 2) load_kv(2, 2);
    CP_COMMIT();

    // hoist Q fragments
    CP_WAIT(3);
    __syncthreads();
    uint32_t qfh[4][4], qfl[4][4];
    {
        const int g = lane >> 3;
        const int qrow = wid * 16 + (lane & 7) + (g & 1) * 8;
#pragma unroll
        for (int kc = 0; kc < 4; kc++) {
            int ch = 2 * kc + (g >> 1);
            ldm_x4(qfh[kc], sb + swzf(qrow, ch));
            ldm_x4(qfl[kc], sb + 16384 + swzf(qrow, ch));
        }
    }

    float oacc[8][4];
#pragma unroll
    for (int u = 0; u < 8; u++)
#pragma unroll
        for (int e = 0; e < 4; e++) oacc[u][e] = 0.f;
    float m0 = -1e30f, m1 = -1e30f, l0 = 0.f, l1 = 0.f;

    const int qw_lo = q0 + wid * 16;
    const int qw_hi = qw_lo + 15;
    const int r0 = qw_lo + (lane >> 2), r1 = r0 + 8;
    const int b_row = lane & 7, b_sel = (lane >> 4) & 1, b_kc = (lane >> 3) & 1;
    const int vrow_base = (lane & 7) + ((lane >> 3) & 1) * 8;
    const int vch_off = lane >> 4;

    for (int it = 0; it < nkt; it++) {
        CP_WAIT(2);
        __syncthreads();
        const int k0 = it * 64;
        const uint32_t st = sb + 32768 + (it & 3) * 32768;

        if (k0 <= qw_hi) {
            // S = Q K^T (3-product fp16 split), into 8 n8-tiles
            float sacc[8][4];
#pragma unroll
            for (int u = 0; u < 8; u++)
#pragma unroll
                for (int e = 0; e < 4; e++) sacc[u][e] = 0.f;
#pragma unroll
            for (int kc = 0; kc < 4; kc++) {
                uint32_t kfh[4][4], kfl[4][4];
#pragma unroll
                for (int u2 = 0; u2 < 4; u2++) {
                    int r = (u2 * 2 + b_sel) * 8 + b_row;
                    int ch = 2 * kc + b_kc;
                    ldm_x4(kfh[u2], st + swzf(r, ch));
                    ldm_x4(kfl[u2], st + 8192 + swzf(r, ch));
                }
#pragma unroll
                for (int u2 = 0; u2 < 4; u2++) {
                    mma_f16(sacc[2*u2],   qfh[kc], &kfh[u2][0]);
                    mma_f16(sacc[2*u2],   qfh[kc], &kfl[u2][0]);
                    mma_f16(sacc[2*u2],   qfl[kc], &kfh[u2][0]);
                    mma_f16(sacc[2*u2+1], qfh[kc], &kfh[u2][2]);
                    mma_f16(sacc[2*u2+1], qfh[kc], &kfl[u2][2]);
                    mma_f16(sacc[2*u2+1], qfl[kc], &kfh[u2][2]);
                }
            }

            // causal mask
            if (k0 + 63 > qw_lo) {
#pragma unroll
                for (int u = 0; u < 8; u++) {
                    int c = k0 + u * 8 + 2 * (lane & 3);
                    if (c     > r0) sacc[u][0] = -1e30f;
                    if (c + 1 > r0) sacc[u][1] = -1e30f;
                    if (c     > r1) sacc[u][2] = -1e30f;
                    if (c + 1 > r1) sacc[u][3] = -1e30f;
                }
            }

            // online softmax (base-2)
            float mx0 = -1e30f, mx1 = -1e30f;
#pragma unroll
            for (int u = 0; u < 8; u++) {
                mx0 = fmaxf(mx0, fmaxf(sacc[u][0], sacc[u][1]));
                mx1 = fmaxf(mx1, fmaxf(sacc[u][2], sacc[u][3]));
            }
            mx0 = fmaxf(mx0, __shfl_xor_sync(0xffffffffu, mx0, 1));
            mx0 = fmaxf(mx0, __shfl_xor_sync(0xffffffffu, mx0, 2));
            mx1 = fmaxf(mx1, __shfl_xor_sync(0xffffffffu, mx1, 1));
            mx1 = fmaxf(mx1, __shfl_xor_sync(0xffffffffu, mx1, 2));
            float mn0 = fmaxf(m0, mx0), mn1 = fmaxf(m1, mx1);
            float a0 = exp2f(m0 - mn0), a1 = exp2f(m1 - mn1);
            float ls0 = 0.f, ls1 = 0.f;
#pragma unroll
            for (int u = 0; u < 8; u++) {
                sacc[u][0] = exp2f(sacc[u][0] - mn0);
                sacc[u][1] = exp2f(sacc[u][1] - mn0);
                sacc[u][2] = exp2f(sacc[u][2] - mn1);
                sacc[u][3] = exp2f(sacc[u][3] - mn1);
                ls0 += sacc[u][0] + sacc[u][1];
                ls1 += sacc[u][2] + sacc[u][3];
            }
            ls0 += __shfl_xor_sync(0xffffffffu, ls0, 1);
            ls0 += __shfl_xor_sync(0xffffffffu, ls0, 2);
            ls1 += __shfl_xor_sync(0xffffffffu, ls1, 1);
            ls1 += __shfl_xor_sync(0xffffffffu, ls1, 2);
            l0 = l0 * a0 + ls0; l1 = l1 * a1 + ls1;
            m0 = mn0; m1 = mn1;
#pragma unroll
            for (int u = 0; u < 8; u++) {
                oacc[u][0] *= a0; oacc[u][1] *= a0;
                oacc[u][2] *= a1; oacc[u][3] *= a1;
            }

            // O += P V (3-product fp16 split; P from registers)
#pragma unroll
            for (int kc = 0; kc < 4; kc++) {
                uint32_t ah[4], al[4];
#pragma unroll
                for (int half_ = 0; half_ < 2; half_++) {
                    const float* s4 = sacc[2 * kc + half_];
                    float h0 = __half2float(__float2half_rn(s4[0]));
                    float h1 = __half2float(__float2half_rn(s4[1]));
                    float h2 = __half2float(__float2half_rn(s4[2]));
                    float h3 = __half2float(__float2half_rn(s4[3]));
                    ah[2*half_]   = packh2(h0, h1);
                    ah[2*half_+1] = packh2(h2, h3);
                    al[2*half_]   = packh2(s4[0] - h0, s4[1] - h1);
                    al[2*half_+1] = packh2(s4[2] - h2, s4[3] - h3);
                }
#pragma unroll
                for (int dnp = 0; dnp < 4; dnp++) {
                    uint32_t vfh[4], vfl[4];
                    int vr = 16 * kc + vrow_base;
                    int vc = 2 * dnp + vch_off;
                    ldm_x4t(vfh, st + 16384 + swzf(vr, vc));
                    ldm_x4t(vfl, st + 24576 + swzf(vr, vc));
                    mma_f16(oacc[2*dnp],   ah, &vfh[0]);
                    mma_f16(oacc[2*dnp],   ah, &vfl[0]);
                    mma_f16(oacc[2*dnp],   al, &vfh[0]);
                    mma_f16(oacc[2*dnp+1], ah, &vfh[2]);
                    mma_f16(oacc[2*dnp+1], ah, &vfl[2]);
                    mma_f16(oacc[2*dnp+1], al, &vfh[2]);
                }
            }
        }

        if (it + 3 < nkt) load_kv(it + 3, (it + 3) & 3);
        CP_COMMIT();
    }

    // epilogue: normalize, bf16 hi/lo split, write head-interleaved [n][q][EE]
    const int n = nh / HH, hd = nh % HH;
    const float il0 = 1.f / l0, il1 = 1.f / l1;
#pragma unroll
    for (int u = 0; u < 8; u++) {
        int d = hd * DD + u * 8 + 2 * (lane & 3);
#pragma unroll
        for (int half_ = 0; half_ < 2; half_++) {
            int row = half_ ? r1 : r0;
            float il = half_ ? il1 : il0;
            float x = oacc[u][2*half_] * il, y = oacc[u][2*half_+1] * il;
            __nv_bfloat16 hx = __float2bfloat16(x), hy = __float2bfloat16(y);
            __nv_bfloat16 lx = __float2bfloat16(x - __bfloat162float(hx));
            __nv_bfloat16 ly = __float2bfloat16(y - __bfloat162float(hy));
            __nv_bfloat16 hp[2] = {hx, hy}, lp[2] = {lx, ly};
            size_t off = ((size_t)(n * LQ + row)) * EE + d;
            *(uint32_t*)(g_ahi + off) = *(const uint32_t*)hp;
            *(uint32_t*)(g_alo + off) = *(const uint32_t*)lp;
        }
    }
}

// ---------------------------------------------------------------------------
extern "C" void kernel_launch(void* const* d_in, const int* in_sizes, int n_in,
                              void* d_out, int out_size)
{
    (void)in_sizes; (void)n_in; (void)out_size;
    const float* q  = (const float*)d_in[0];
    const float* k  = (const float*)d_in[1];
    const float* v  = (const float*)d_in[2];
    const float* wq = (const float*)d_in[3];
    const float* wk = (const float*)d_in[4];
    const float* wv = (const float*)d_in[5];
    const float* wo = (const float*)d_in[6];
    float* out = (float*)d_out;

    __nv_bfloat16 *xhi, *xlo, *whi, *wlo, *ahi, *alo;
    __half *qh, *ql, *kh, *kl, *vh, *vl;
    cudaGetSymbolAddress((void**)&xhi, g_xhi);
    cudaGetSymbolAddress((void**)&xlo, g_xlo);
    cudaGetSymbolAddress((void**)&whi, g_whi);
    cudaGetSymbolAddress((void**)&wlo, g_wlo);
    cudaGetSymbolAddress((void**)&ahi, g_ahi);
    cudaGetSymbolAddress((void**)&alo, g_alo);
    cudaGetSymbolAddress((void**)&qh,  g_qh);
    cudaGetSymbolAddress((void**)&ql,  g_ql);
    cudaGetSymbolAddress((void**)&kh,  g_kh);
    cudaGetSymbolAddress((void**)&kl,  g_kl);
    cudaGetSymbolAddress((void**)&vh,  g_vh);
    cudaGetSymbolAddress((void**)&vl,  g_vl);

    cudaFuncSetAttribute(gemm_mma, cudaFuncAttributeMaxDynamicSharedMemorySize, GEMM_SMEM);
    cudaFuncSetAttribute(flash_mma, cudaFuncAttributeMaxDynamicSharedMemorySize, FLASH_SMEM);

    const size_t NX = (size_t)NL * GK;
    const size_t NW = (size_t)GK * GK;
    const int TB = 256;
    split_kernel<<<(int)(NX/4 + TB - 1)/TB, TB>>>(q,  xhi,        xlo,        (int)(NX/4));
    split_kernel<<<(int)(NX/4 + TB - 1)/TB, TB>>>(k,  xhi + NX,   xlo + NX,   (int)(NX/4));
    split_kernel<<<(int)(NX/4 + TB - 1)/TB, TB>>>(v,  xhi + 2*NX, xlo + 2*NX, (int)(NX/4));
    split_kernel<<<(int)(NW/4 + TB - 1)/TB, TB>>>(wq, whi,        wlo,        (int)(NW/4));
    split_kernel<<<(int)(NW/4 + TB - 1)/TB, TB>>>(wk, whi + NW,   wlo + NW,   (int)(NW/4));
    split_kernel<<<(int)(NW/4 + TB - 1)/TB, TB>>>(wv, whi + 2*NW, wlo + 2*NW, (int)(NW/4));
    split_kernel<<<(int)(NW/4 + TB - 1)/TB, TB>>>(wo, whi + 3*NW, wlo + 3*NW, (int)(NW/4));

    dim3 gg(EE / 128, NL / 128);
    gemm_mma<<<gg, 256, GEMM_SMEM>>>(xhi,        xlo,        whi,        wlo,
                                     nullptr, qh, ql, 1, QSCALE);
    gemm_mma<<<gg, 256, GEMM_SMEM>>>(xhi + NX,   xlo + NX,   whi + NW,   wlo + NW,
                                     nullptr, kh, kl, 1, 1.0f);
    gemm_mma<<<gg, 256, GEMM_SMEM>>>(xhi + 2*NX, xlo + 2*NX, whi + 2*NW, wlo + 2*NW,
                                     nullptr, vh, vl, 1, 1.0f);

    flash_mma<<<dim3(16, NB * HH), 256, FLASH_SMEM>>>();

    gemm_mma<<<gg, 256, GEMM_SMEM>>>(ahi, alo, whi + 3*NW, wlo + 3*NW,
                                     out, nullptr, nullptr, 0, 1.0f);
}

// round 7
// speedup vs baseline: 3.3829x; 1.1255x over previous
#include <cuda_runtime.h>
#include <cuda_bf16.h>
#include <cuda_fp16.h>
#include <cstdint>
#include <math.h>

#define NB 4
#define LQ 2048
#define EE 1024
#define HH 16
#define DD 64
#define NL (NB*LQ)   /* 8192 */
#define GK EE        /* 1024 */

// log2(e)/sqrt(64): folded into Q so softmax uses exp2
#define QSCALE 0.18033688011112042f

// ---------------------------------------------------------------------------
// Scratch (allocation-free rule: __device__ globals)
// ---------------------------------------------------------------------------
__device__ __nv_bfloat16 g_xhi[(size_t)3*NL*GK];   // q,k,v inputs hi (bf16, GEMM A)
__device__ __nv_bfloat16 g_xlo[(size_t)3*NL*GK];
__device__ __nv_bfloat16 g_whi[(size_t)4*GK*GK];   // wq,wk,wv,wo hi
__device__ __nv_bfloat16 g_wlo[(size_t)4*GK*GK];
__device__ __half g_qh[(size_t)NL*GK];             // head-major fp16 hi/lo
__device__ __half g_ql[(size_t)NL*GK];
__device__ __half g_kh[(size_t)NL*GK];
__device__ __half g_kl[(size_t)NL*GK];
__device__ __half g_vh[(size_t)NL*GK];
__device__ __half g_vl[(size_t)NL*GK];
__device__ __nv_bfloat16 g_ahi[(size_t)NL*GK];     // attention out hi/lo (bf16)
__device__ __nv_bfloat16 g_alo[(size_t)NL*GK];

// ---------------------------------------------------------------------------
// common PTX helpers
// ---------------------------------------------------------------------------
__device__ __forceinline__ void cp16(uint32_t smem, const void* g) {
    asm volatile("cp.async.cg.shared.global [%0], [%1], 16;" :: "r"(smem), "l"(g));
}
#define CP_COMMIT() asm volatile("cp.async.commit_group;" ::: "memory")
#define CP_WAIT(n)  asm volatile("cp.async.wait_group %0;" :: "n"(n) : "memory")

__device__ __forceinline__ void ldm_x4(uint32_t* r, uint32_t addr) {
    asm volatile("ldmatrix.sync.aligned.m8n8.x4.shared.b16 {%0,%1,%2,%3}, [%4];"
                 : "=r"(r[0]), "=r"(r[1]), "=r"(r[2]), "=r"(r[3]) : "r"(addr));
}
__device__ __forceinline__ void ldm_x4t(uint32_t* r, uint32_t addr) {
    asm volatile("ldmatrix.sync.aligned.m8n8.x4.trans.shared.b16 {%0,%1,%2,%3}, [%4];"
                 : "=r"(r[0]), "=r"(r[1]), "=r"(r[2]), "=r"(r[3]) : "r"(addr));
}
__device__ __forceinline__ void mma_bf16(float* d, const uint32_t* a, const uint32_t* b) {
    asm volatile("mma.sync.aligned.m16n8k16.row.col.f32.bf16.bf16.f32 "
                 "{%0,%1,%2,%3}, {%4,%5,%6,%7}, {%8,%9}, {%0,%1,%2,%3};"
                 : "+f"(d[0]), "+f"(d[1]), "+f"(d[2]), "+f"(d[3])
                 : "r"(a[0]), "r"(a[1]), "r"(a[2]), "r"(a[3]), "r"(b[0]), "r"(b[1]));
}
__device__ __forceinline__ void mma_f16(float* d, const uint32_t* a, const uint32_t* b) {
    asm volatile("mma.sync.aligned.m16n8k16.row.col.f32.f16.f16.f32 "
                 "{%0,%1,%2,%3}, {%4,%5,%6,%7}, {%8,%9}, {%0,%1,%2,%3};"
                 : "+f"(d[0]), "+f"(d[1]), "+f"(d[2]), "+f"(d[3])
                 : "r"(a[0]), "r"(a[1]), "r"(a[2]), "r"(a[3]), "r"(b[0]), "r"(b[1]));
}
__device__ __forceinline__ uint32_t packh2(float lo, float hi) {
    uint32_t r;
    asm("cvt.rn.f16x2.f32 %0, %1, %2;" : "=r"(r) : "f"(hi), "f"(lo));
    return r;
}

// ---------------------------------------------------------------------------
// Fused splits fp32 -> bf16 hi/lo (grid.y selects the tensor)
// ---------------------------------------------------------------------------
__device__ __forceinline__ void split_one(const float* __restrict__ x,
                                          __nv_bfloat16* __restrict__ hi,
                                          __nv_bfloat16* __restrict__ lo, int i) {
    float4 v = ((const float4*)x)[i];
    float f[4] = {v.x, v.y, v.z, v.w};
    __nv_bfloat16 h[4], l[4];
#pragma unroll
    for (int j = 0; j < 4; j++) {
        h[j] = __float2bfloat16(f[j]);
        l[j] = __float2bfloat16(f[j] - __bfloat162float(h[j]));
    }
    *(uint2*)(hi + (size_t)4 * i) = *(const uint2*)h;
    *(uint2*)(lo + (size_t)4 * i) = *(const uint2*)l;
}

__global__ void split3_kernel(const float* __restrict__ a, const float* __restrict__ b,
                              const float* __restrict__ c,
                              __nv_bfloat16* __restrict__ hi,
                              __nv_bfloat16* __restrict__ lo, int n4) {
    int i = blockIdx.x * blockDim.x + threadIdx.x;
    if (i >= n4) return;
    int t = blockIdx.y;
    const float* src = (t == 0) ? a : (t == 1) ? b : c;
    size_t off = (size_t)t * n4;
    split_one(src, hi + 4 * off, lo + 4 * off, i);
}

__global__ void split4_kernel(const float* __restrict__ a, const float* __restrict__ b,
                              const float* __restrict__ c, const float* __restrict__ d,
                              __nv_bfloat16* __restrict__ hi,
                              __nv_bfloat16* __restrict__ lo, int n4) {
    int i = blockIdx.x * blockDim.x + threadIdx.x;
    if (i >= n4) return;
    int t = blockIdx.y;
    const float* src = (t == 0) ? a : (t == 1) ? b : (t == 2) ? c : d;
    size_t off = (size_t)t * n4;
    split_one(src, hi + 4 * off, lo + 4 * off, i);
}

// ---------------------------------------------------------------------------
// bf16 mma.sync GEMM: C[8192,1024] = A @ B^T, 3-product hi/lo split.
// Tile 128x128, BK=32, 128 threads (4 warps, 64x64 each), 4-stage cp.async.
// mode 0: fp32 C[row][EE].  mode 1: fp16 hi/lo head-major [(n*HH+h)*LQ+l][d], *scale.
// ---------------------------------------------------------------------------
__device__ __forceinline__ uint32_t swzg(int row, int kc) {  // 64B rows, 2/line
    int line = row >> 1;
    int slot = (((row & 1) << 2) | kc) ^ (line & 7);
    return (uint32_t)(line * 128 + slot * 16);
}

#define NITER 96   /* 3 passes * 32 k-tiles */
#define GEMM_SMEM (4 * 16384)

__global__ __launch_bounds__(128)
void gemm_mma(const __nv_bfloat16* __restrict__ Ah, const __nv_bfloat16* __restrict__ Al,
              const __nv_bfloat16* __restrict__ Bh, const __nv_bfloat16* __restrict__ Bl,
              float* __restrict__ C, __half* __restrict__ Chi, __half* __restrict__ Clo,
              int mode, float scale)
{
    extern __shared__ char smg[];
    const uint32_t sb = (uint32_t)__cvta_generic_to_shared(smg);

    const int tid = threadIdx.x;
    const int wid = tid >> 5, lane = tid & 31;
    const int wm = wid & 1, wn = wid >> 1;      // 2x2 warps, 64x64 tiles
    const int m0 = wm * 64, n0 = wn * 64;
    const int row0 = blockIdx.y * 128, col0 = blockIdx.x * 128;

    const __nv_bfloat16* Ap[3] = {Ah, Ah, Al};
    const __nv_bfloat16* Bp[3] = {Bh, Bl, Bh};

    float acc[4][8][4];
#pragma unroll
    for (int t = 0; t < 4; t++)
#pragma unroll
        for (int u = 0; u < 8; u++)
#pragma unroll
            for (int e = 0; e < 4; e++) acc[t][u][e] = 0.f;

    auto load_tile = [&](int it, int s) {
        const __nv_bfloat16* Abase = Ap[it >> 5];
        const __nv_bfloat16* Bbase = Bp[it >> 5];
        const int kt = (it & 31) << 5;
        const uint32_t sA = sb + s * 16384, sB = sA + 8192;
#pragma unroll
        for (int j = 0; j < 4; j++) {
            int c = tid + j * 128;               // 0..511
            int row = c >> 2, kc = c & 3;
            uint32_t so = swzg(row, kc);
            cp16(sA + so, Abase + (size_t)(row0 + row) * GK + kt + kc * 8);
            cp16(sB + so, Bbase + (size_t)(col0 + row) * GK + kt + kc * 8);
        }
    };

    load_tile(0, 0); CP_COMMIT();
    load_tile(1, 1); CP_COMMIT();
    load_tile(2, 2); CP_COMMIT();

    const int a_row = lane & 15;
    const int a_kc  = lane >> 4;
    const int b_row = lane & 7;
    const int b_sel = (lane >> 4) & 1;
    const int b_kc  = (lane >> 3) & 1;

    for (int it = 0; it < NITER; it++) {
        const int bu = it & 3;
        const uint32_t sA = sb + bu * 16384, sB = sA + 8192;
        CP_WAIT(2);
        __syncthreads();

#pragma unroll
        for (int s = 0; s < 2; s++) {
            uint32_t af[4][4], bf[8][2];
#pragma unroll
            for (int t = 0; t < 4; t++)
                ldm_x4(af[t], sA + swzg(m0 + t * 16 + a_row, 2 * s + a_kc));
#pragma unroll
            for (int u2 = 0; u2 < 4; u2++) {
                uint32_t r4[4];
                ldm_x4(r4, sB + swzg(n0 + (u2 * 2 + b_sel) * 8 + b_row, 2 * s + b_kc));
                bf[u2*2][0] = r4[0]; bf[u2*2][1] = r4[1];
                bf[u2*2+1][0] = r4[2]; bf[u2*2+1][1] = r4[3];
            }
#pragma unroll
            for (int t = 0; t < 4; t++)
#pragma unroll
                for (int u = 0; u < 8; u++)
                    mma_bf16(acc[t][u], af[t], bf[u]);
        }

        if (it + 3 < NITER) load_tile(it + 3, (it + 3) & 3);
        CP_COMMIT();
    }

    const int er = lane >> 2, ec = (lane & 3) * 2;
#pragma unroll
    for (int t = 0; t < 4; t++) {
#pragma unroll
        for (int u = 0; u < 8; u++) {
            int col = col0 + n0 + u * 8 + ec;
#pragma unroll
            for (int half_ = 0; half_ < 2; half_++) {
                int row = row0 + m0 + t * 16 + er + half_ * 8;
                float x = acc[t][u][half_*2] * scale, y = acc[t][u][half_*2+1] * scale;
                if (mode == 0) {
                    *(float2*)(C + (size_t)row * EE + col) = make_float2(x, y);
                } else {
                    int n = row >> 11, l = row & 2047;
                    int hh = col >> 6, d = col & 63;
                    size_t off = ((size_t)((n * HH + hh) * LQ + l)) * DD + d;
                    __half hx = __float2half_rn(x), hy = __float2half_rn(y);
                    __half lx = __float2half_rn(x - __half2float(hx));
                    __half ly = __float2half_rn(y - __half2float(hy));
                    __half hp[2] = {hx, hy}, lp[2] = {lx, ly};
                    *(uint32_t*)(Chi + off) = *(const uint32_t*)hp;
                    *(uint32_t*)(Clo + off) = *(const uint32_t*)lp;
                }
            }
        }
    }
}

// ---------------------------------------------------------------------------
// Flash attention with mma.sync fp16. QK^T: 3-product hi/lo. PV: 2-product
// (P fp16 single + V hi/lo; P rounding error ~3e-4 rel, inside 1e-3 gate).
// Block = 128 q rows x one (n,h). 8 warps x 16 q rows. k-tiles of 64, 4-stage.
// smem: Qh 0, Ql 16K, stage s at 32K+s*32K: {Kh, Kl, Vh, Vl} x 8K.
// ---------------------------------------------------------------------------
__device__ __forceinline__ uint32_t swzf(int row, int ch) {  // 128B rows
    return (uint32_t)(row * 128 + ((ch ^ (row & 7)) << 4));
}
#define FLASH_SMEM (32768 + 4 * 32768)

__global__ __launch_bounds__(256)
void flash_mma()
{
    extern __shared__ char smf[];
    const uint32_t sb = (uint32_t)__cvta_generic_to_shared(smf);
    const int tid = threadIdx.x;
    const int wid = tid >> 5, lane = tid & 31;
    const int qb = 15 - (int)blockIdx.x;      // heavy blocks first
    const int nh = blockIdx.y;
    const int q0 = qb * 128;
    const int nkt = 2 * (qb + 1);

    const size_t hb = (size_t)nh * LQ * DD;
    const __half* Qhg = g_qh + hb; const __half* Qlg = g_ql + hb;
    const __half* Khg = g_kh + hb; const __half* Klg = g_kl + hb;
    const __half* Vhg = g_vh + hb; const __half* Vlg = g_vl + hb;

    // Q (hi+lo): 2048 16B chunks
#pragma unroll
    for (int j = 0; j < 8; j++) {
        int c = tid + j * 256;
        int tsr = c >> 10, cc = c & 1023, row = cc >> 3, ch = cc & 7;
        const __half* src = tsr ? Qlg : Qhg;
        cp16(sb + tsr * 16384 + swzf(row, ch), src + (size_t)(q0 + row) * DD + ch * 8);
    }
    CP_COMMIT();

    auto load_kv = [&](int jt, int s) {
        const int k0 = jt * 64;
        const uint32_t stb = sb + 32768 + s * 32768;
#pragma unroll
        for (int j = 0; j < 8; j++) {
            int c = tid + j * 256;
            int tsr = c >> 9, cc = c & 511, row = cc >> 3, ch = cc & 7;
            const __half* src = (tsr == 0) ? Khg : (tsr == 1) ? Klg : (tsr == 2) ? Vhg : Vlg;
            cp16(stb + tsr * 8192 + swzf(row, ch), src + (size_t)(k0 + row) * DD + ch * 8);
        }
    };
    load_kv(0, 0); CP_COMMIT();
    if (nkt > 1) load_kv(1, 1);
    CP_COMMIT();
    if (nkt > 2) load_kv(2, 2);
    CP_COMMIT();

    // hoist Q fragments
    CP_WAIT(3);
    __syncthreads();
    uint32_t qfh[4][4], qfl[4][4];
    {
        const int g = lane >> 3;
        const int qrow = wid * 16 + (lane & 7) + (g & 1) * 8;
#pragma unroll
        for (int kc = 0; kc < 4; kc++) {
            int ch = 2 * kc + (g >> 1);
            ldm_x4(qfh[kc], sb + swzf(qrow, ch));
            ldm_x4(qfl[kc], sb + 16384 + swzf(qrow, ch));
        }
    }

    float oacc[8][4];
#pragma unroll
    for (int u = 0; u < 8; u++)
#pragma unroll
        for (int e = 0; e < 4; e++) oacc[u][e] = 0.f;
    float m0 = -1e30f, m1 = -1e30f, l0 = 0.f, l1 = 0.f;

    const int qw_lo = q0 + wid * 16;
    const int qw_hi = qw_lo + 15;
    const int r0 = qw_lo + (lane >> 2), r1 = r0 + 8;
    const int b_row = lane & 7, b_sel = (lane >> 4) & 1, b_kc = (lane >> 3) & 1;
    const int vrow_base = (lane & 7) + ((lane >> 3) & 1) * 8;
    const int vch_off = lane >> 4;

    for (int it = 0; it < nkt; it++) {
        CP_WAIT(2);
        __syncthreads();
        const int k0 = it * 64;
        const uint32_t st = sb + 32768 + (it & 3) * 32768;

        if (k0 <= qw_hi) {
            // S = Q K^T (3-product fp16 split), into 8 n8-tiles
            float sacc[8][4];
#pragma unroll
            for (int u = 0; u < 8; u++)
#pragma unroll
                for (int e = 0; e < 4; e++) sacc[u][e] = 0.f;
#pragma unroll
            for (int kc = 0; kc < 4; kc++) {
                uint32_t kfh[4][4], kfl[4][4];
#pragma unroll
                for (int u2 = 0; u2 < 4; u2++) {
                    int r = (u2 * 2 + b_sel) * 8 + b_row;
                    int ch = 2 * kc + b_kc;
                    ldm_x4(kfh[u2], st + swzf(r, ch));
                    ldm_x4(kfl[u2], st + 8192 + swzf(r, ch));
                }
#pragma unroll
                for (int u2 = 0; u2 < 4; u2++) {
                    mma_f16(sacc[2*u2],   qfh[kc], &kfh[u2][0]);
                    mma_f16(sacc[2*u2],   qfh[kc], &kfl[u2][0]);
                    mma_f16(sacc[2*u2],   qfl[kc], &kfh[u2][0]);
                    mma_f16(sacc[2*u2+1], qfh[kc], &kfh[u2][2]);
                    mma_f16(sacc[2*u2+1], qfh[kc], &kfl[u2][2]);
                    mma_f16(sacc[2*u2+1], qfl[kc], &kfh[u2][2]);
                }
            }

            // causal mask
            if (k0 + 63 > qw_lo) {
#pragma unroll
                for (int u = 0; u < 8; u++) {
                    int c = k0 + u * 8 + 2 * (lane & 3);
                    if (c     > r0) sacc[u][0] = -1e30f;
                    if (c + 1 > r0) sacc[u][1] = -1e30f;
                    if (c     > r1) sacc[u][2] = -1e30f;
                    if (c + 1 > r1) sacc[u][3] = -1e30f;
                }
            }

            // online softmax (base-2)
            float mx0 = -1e30f, mx1 = -1e30f;
#pragma unroll
            for (int u = 0; u < 8; u++) {
                mx0 = fmaxf(mx0, fmaxf(sacc[u][0], sacc[u][1]));
                mx1 = fmaxf(mx1, fmaxf(sacc[u][2], sacc[u][3]));
            }
            mx0 = fmaxf(mx0, __shfl_xor_sync(0xffffffffu, mx0, 1));
            mx0 = fmaxf(mx0, __shfl_xor_sync(0xffffffffu, mx0, 2));
            mx1 = fmaxf(mx1, __shfl_xor_sync(0xffffffffu, mx1, 1));
            mx1 = fmaxf(mx1, __shfl_xor_sync(0xffffffffu, mx1, 2));
            float mn0 = fmaxf(m0, mx0), mn1 = fmaxf(m1, mx1);
            float a0 = exp2f(m0 - mn0), a1 = exp2f(m1 - mn1);
            float ls0 = 0.f, ls1 = 0.f;
#pragma unroll
            for (int u = 0; u < 8; u++) {
                sacc[u][0] = exp2f(sacc[u][0] - mn0);
                sacc[u][1] = exp2f(sacc[u][1] - mn0);
                sacc[u][2] = exp2f(sacc[u][2] - mn1);
                sacc[u][3] = exp2f(sacc[u][3] - mn1);
                ls0 += sacc[u][0] + sacc[u][1];
                ls1 += sacc[u][2] + sacc[u][3];
            }
            ls0 += __shfl_xor_sync(0xffffffffu, ls0, 1);
            ls0 += __shfl_xor_sync(0xffffffffu, ls0, 2);
            ls1 += __shfl_xor_sync(0xffffffffu, ls1, 1);
            ls1 += __shfl_xor_sync(0xffffffffu, ls1, 2);
            l0 = l0 * a0 + ls0; l1 = l1 * a1 + ls1;
            m0 = mn0; m1 = mn1;
#pragma unroll
            for (int u = 0; u < 8; u++) {
                oacc[u][0] *= a0; oacc[u][1] *= a0;
                oacc[u][2] *= a1; oacc[u][3] *= a1;
            }

            // O += P V (P fp16 single-product + V hi/lo)
#pragma unroll
            for (int kc = 0; kc < 4; kc++) {
                uint32_t ah[4];
#pragma unroll
                for (int half_ = 0; half_ < 2; half_++) {
                    const float* s4 = sacc[2 * kc + half_];
                    ah[2*half_]   = packh2(s4[0], s4[1]);
                    ah[2*half_+1] = packh2(s4[2], s4[3]);
                }
#pragma unroll
                for (int dnp = 0; dnp < 4; dnp++) {
                    uint32_t vfh[4], vfl[4];
                    int vr = 16 * kc + vrow_base;
                    int vc = 2 * dnp + vch_off;
                    ldm_x4t(vfh, st + 16384 + swzf(vr, vc));
                    ldm_x4t(vfl, st + 24576 + swzf(vr, vc));
                    mma_f16(oacc[2*dnp],   ah, &vfh[0]);
                    mma_f16(oacc[2*dnp],   ah, &vfl[0]);
                    mma_f16(oacc[2*dnp+1], ah, &vfh[2]);
                    mma_f16(oacc[2*dnp+1], ah, &vfl[2]);
                }
            }
        }

        if (it + 3 < nkt) load_kv(it + 3, (it + 3) & 3);
        CP_COMMIT();
    }

    // epilogue: normalize, bf16 hi/lo split, write head-interleaved [n][q][EE]
    const int n = nh / HH, hd = nh % HH;
    const float il0 = 1.f / l0, il1 = 1.f / l1;
#pragma unroll
    for (int u = 0; u < 8; u++) {
        int d = hd * DD + u * 8 + 2 * (lane & 3);
#pragma unroll
        for (int half_ = 0; half_ < 2; half_++) {
            int row = half_ ? r1 : r0;
            float il = half_ ? il1 : il0;
            float x = oacc[u][2*half_] * il, y = oacc[u][2*half_+1] * il;
            __nv_bfloat16 hx = __float2bfloat16(x), hy = __float2bfloat16(y);
            __nv_bfloat16 lx = __float2bfloat16(x - __bfloat162float(hx));
            __nv_bfloat16 ly = __float2bfloat16(y - __bfloat162float(hy));
            __nv_bfloat16 hp[2] = {hx, hy}, lp[2] = {lx, ly};
            size_t off = ((size_t)(n * LQ + row)) * EE + d;
            *(uint32_t*)(g_ahi + off) = *(const uint32_t*)hp;
            *(uint32_t*)(g_alo + off) = *(const uint32_t*)lp;
        }
    }
}

// ---------------------------------------------------------------------------
extern "C" void kernel_launch(void* const* d_in, const int* in_sizes, int n_in,
                              void* d_out, int out_size)
{
    (void)in_sizes; (void)n_in; (void)out_size;
    const float* q  = (const float*)d_in[0];
    const float* k  = (const float*)d_in[1];
    const float* v  = (const float*)d_in[2];
    const float* wq = (const float*)d_in[3];
    const float* wk = (const float*)d_in[4];
    const float* wv = (const float*)d_in[5];
    const float* wo = (const float*)d_in[6];
    float* out = (float*)d_out;

    __nv_bfloat16 *xhi, *xlo, *whi, *wlo, *ahi, *alo;
    __half *qh, *ql, *kh, *kl, *vh, *vl;
    cudaGetSymbolAddress((void**)&xhi, g_xhi);
    cudaGetSymbolAddress((void**)&xlo, g_xlo);
    cudaGetSymbolAddress((void**)&whi, g_whi);
    cudaGetSymbolAddress((void**)&wlo, g_wlo);
    cudaGetSymbolAddress((void**)&ahi, g_ahi);
    cudaGetSymbolAddress((void**)&alo, g_alo);
    cudaGetSymbolAddress((void**)&qh,  g_qh);
    cudaGetSymbolAddress((void**)&ql,  g_ql);
    cudaGetSymbolAddress((void**)&kh,  g_kh);
    cudaGetSymbolAddress((void**)&kl,  g_kl);
    cudaGetSymbolAddress((void**)&vh,  g_vh);
    cudaGetSymbolAddress((void**)&vl,  g_vl);

    cudaFuncSetAttribute(gemm_mma, cudaFuncAttributeMaxDynamicSharedMemorySize, GEMM_SMEM);
    cudaFuncSetAttribute(flash_mma, cudaFuncAttributeMaxDynamicSharedMemorySize, FLASH_SMEM);

    const size_t NX = (size_t)NL * GK;
    const size_t NW = (size_t)GK * GK;
    const int TB = 256;
    // launch order matters for ncu (-s 5 -c 1): flash_mma is launch index 5
    split3_kernel<<<dim3((int)(NX/4 + TB - 1)/TB, 3), TB>>>(q, k, v, xhi, xlo, (int)(NX/4));
    split4_kernel<<<dim3((int)(NW/4 + TB - 1)/TB, 4), TB>>>(wq, wk, wv, wo, whi, wlo, (int)(NW/4));

    dim3 gg(EE / 128, NL / 128);
    gemm_mma<<<gg, 128, GEMM_SMEM>>>(xhi,        xlo,        whi,        wlo,
                                     nullptr, qh, ql, 1, QSCALE);
    gemm_mma<<<gg, 128, GEMM_SMEM>>>(xhi + NX,   xlo + NX,   whi + NW,   wlo + NW,
                                     nullptr, kh, kl, 1, 1.0f);
    gemm_mma<<<gg, 128, GEMM_SMEM>>>(xhi + 2*NX, xlo + 2*NX, whi + 2*NW, wlo + 2*NW,
                                     nullptr, vh, vl, 1, 1.0f);

    flash_mma<<<dim3(16, NB * HH), 256, FLASH_SMEM>>>();

    gemm_mma<<<gg, 128, GEMM_SMEM>>>(ahi, alo, whi + 3*NW, wlo + 3*NW,
                                     out, nullptr, nullptr, 0, 1.0f);
}

// round 10
// speedup vs baseline: 4.1119x; 1.2155x over previous
#include <cuda_runtime.h>
#include <cuda_fp16.h>
#include <cstdint>
#include <math.h>

#define NB 4
#define LQ 2048
#define EE 1024
#define HH 16
#define DD 64
#define NL (NB*LQ)   /* 8192 */
#define GK EE        /* 1024 */

// log2(e)/sqrt(64): folded into Q so softmax uses exp2
#define QSCALE 0.18033688011112042f

// ---------------------------------------------------------------------------
// Scratch (allocation-free rule: __device__ globals) — fp16 hi/lo
// ---------------------------------------------------------------------------
__device__ __half g_xhi[(size_t)3*NL*GK];   // q,k,v inputs hi (GEMM A)
__device__ __half g_xlo[(size_t)3*NL*GK];
__device__ __half g_whi[(size_t)4*GK*GK];   // wq,wk,wv,wo hi
__device__ __half g_wlo[(size_t)4*GK*GK];
__device__ __half g_qh[(size_t)NL*GK];      // head-major fp16 hi/lo
__device__ __half g_ql[(size_t)NL*GK];
__device__ __half g_kh[(size_t)NL*GK];
__device__ __half g_kl[(size_t)NL*GK];
__device__ __half g_vh[(size_t)NL*GK];
__device__ __half g_vl[(size_t)NL*GK];
__device__ __half g_ahi[(size_t)NL*GK];     // attention out hi/lo
__device__ __half g_alo[(size_t)NL*GK];

// ---------------------------------------------------------------------------
// common PTX helpers
// ---------------------------------------------------------------------------
__device__ __forceinline__ void cp16(uint32_t smem, const void* g) {
    asm volatile("cp.async.cg.shared.global [%0], [%1], 16;" :: "r"(smem), "l"(g));
}
#define CP_COMMIT() asm volatile("cp.async.commit_group;" ::: "memory")
#define CP_WAIT(n)  asm volatile("cp.async.wait_group %0;" :: "n"(n) : "memory")

__device__ __forceinline__ void ldm_x4(uint32_t* r, uint32_t addr) {
    asm volatile("ldmatrix.sync.aligned.m8n8.x4.shared.b16 {%0,%1,%2,%3}, [%4];"
                 : "=r"(r[0]), "=r"(r[1]), "=r"(r[2]), "=r"(r[3]) : "r"(addr));
}
__device__ __forceinline__ void ldm_x4t(uint32_t* r, uint32_t addr) {
    asm volatile("ldmatrix.sync.aligned.m8n8.x4.trans.shared.b16 {%0,%1,%2,%3}, [%4];"
                 : "=r"(r[0]), "=r"(r[1]), "=r"(r[2]), "=r"(r[3]) : "r"(addr));
}
__device__ __forceinline__ void mma_f16(float* d, const uint32_t* a, const uint32_t* b) {
    asm volatile("mma.sync.aligned.m16n8k16.row.col.f32.f16.f16.f32 "
                 "{%0,%1,%2,%3}, {%4,%5,%6,%7}, {%8,%9}, {%0,%1,%2,%3};"
                 : "+f"(d[0]), "+f"(d[1]), "+f"(d[2]), "+f"(d[3])
                 : "r"(a[0]), "r"(a[1]), "r"(a[2]), "r"(a[3]), "r"(b[0]), "r"(b[1]));
}
__device__ __forceinline__ uint32_t packh2(float lo, float hi) {
    uint32_t r;
    asm("cvt.rn.f16x2.f32 %0, %1, %2;" : "=r"(r) : "f"(hi), "f"(lo));
    return r;
}

// ---------------------------------------------------------------------------
// ONE fused split kernel: fp32 -> fp16 hi/lo for 7 tensors (grid.y selects)
// ---------------------------------------------------------------------------
__device__ __forceinline__ void split_one(const float* __restrict__ x,
                                          __half* __restrict__ hi,
                                          __half* __restrict__ lo, int i) {
    float4 v = ((const float4*)x)[i];
    float f[4] = {v.x, v.y, v.z, v.w};
    __half h[4], l[4];
#pragma unroll
    for (int j = 0; j < 4; j++) {
        h[j] = __float2half_rn(f[j]);
        l[j] = __float2half_rn(f[j] - __half2float(h[j]));
    }
    *(uint2*)(hi + (size_t)4 * i) = *(const uint2*)h;
    *(uint2*)(lo + (size_t)4 * i) = *(const uint2*)l;
}

__global__ void split_all(const float* __restrict__ q, const float* __restrict__ k,
                          const float* __restrict__ v, const float* __restrict__ wq,
                          const float* __restrict__ wk, const float* __restrict__ wv,
                          const float* __restrict__ wo, int n4x, int n4w)
{
    const int t = blockIdx.y;
    const int i = blockIdx.x * blockDim.x + threadIdx.x;
    if (t < 3) {
        if (i >= n4x) return;
        const float* src = (t == 0) ? q : (t == 1) ? k : v;
        size_t off = (size_t)4 * t * n4x;
        split_one(src, g_xhi + off, g_xlo + off, i);
    } else {
        if (i >= n4w) return;
        int w = t - 3;
        const float* src = (w == 0) ? wq : (w == 1) ? wk : (w == 2) ? wv : wo;
        size_t off = (size_t)4 * w * n4w;
        split_one(src, g_whi + off, g_wlo + off, i);
    }
}

// ---------------------------------------------------------------------------
// fp16 mma.sync GEMM: C[8192,1024] = A @ B^T, 2-product hi/lo split:
//   C = Ah*Bh + Ah*Bl   (= Ah*B exactly; dropped Al*B ~ 1.4e-4 rel)
// Tile 128x128, BK=32, 128 threads (4 warps, 64x64 each), 4-stage cp.async.
// mode 0: fp32 C[row][EE].  mode 1: fp16 hi/lo head-major, *scale.
// ---------------------------------------------------------------------------
__device__ __forceinline__ uint32_t swzg(int row, int kc) {  // 64B rows, 2/line
    int line = row >> 1;
    int slot = (((row & 1) << 2) | kc) ^ (line & 7);
    return (uint32_t)(line * 128 + slot * 16);
}

#define NITER 64   /* 2 passes * 32 k-tiles */
#define GEMM_SMEM (4 * 16384)

__global__ __launch_bounds__(128)
void gemm_mma(const __half* __restrict__ Ah, const __half* __restrict__ Bh,
              const __half* __restrict__ Bl,
              float* __restrict__ C, __half* __restrict__ Chi, __half* __restrict__ Clo,
              int mode, float scale)
{
    extern __shared__ char smg[];
    const uint32_t sb = (uint32_t)__cvta_generic_to_shared(smg);

    const int tid = threadIdx.x;
    const int wid = tid >> 5, lane = tid & 31;
    const int wm = wid & 1, wn = wid >> 1;      // 2x2 warps, 64x64 tiles
    const int m0 = wm * 64, n0 = wn * 64;
    const int row0 = blockIdx.y * 128, col0 = blockIdx.x * 128;

    const __half* Bp[2] = {Bh, Bl};

    float acc[4][8][4];
#pragma unroll
    for (int t = 0; t < 4; t++)
#pragma unroll
        for (int u = 0; u < 8; u++)
#pragma unroll
            for (int e = 0; e < 4; e++) acc[t][u][e] = 0.f;

    auto load_tile = [&](int it, int s) {
        const __half* Bbase = Bp[it >> 5];
        const int kt = (it & 31) << 5;
        const uint32_t sA = sb + s * 16384, sB = sA + 8192;
#pragma unroll
        for (int j = 0; j < 4; j++) {
            int c = tid + j * 128;               // 0..511
            int row = c >> 2, kc = c & 3;
            uint32_t so = swzg(row, kc);
            cp16(sA + so, Ah + (size_t)(row0 + row) * GK + kt + kc * 8);
            cp16(sB + so, Bbase + (size_t)(col0 + row) * GK + kt + kc * 8);
        }
    };

    load_tile(0, 0); CP_COMMIT();
    load_tile(1, 1); CP_COMMIT();
    load_tile(2, 2); CP_COMMIT();

    const int a_row = lane & 15;
    const int a_kc  = lane >> 4;
    const int b_row = lane & 7;
    const int b_sel = (lane >> 4) & 1;
    const int b_kc  = (lane >> 3) & 1;

    for (int it = 0; it < NITER; it++) {
        const int bu = it & 3;
        const uint32_t sA = sb + bu * 16384, sB = sA + 8192;
        CP_WAIT(2);
        __syncthreads();

#pragma unroll
        for (int s = 0; s < 2; s++) {
            uint32_t af[4][4], bf[8][2];
#pragma unroll
            for (int t = 0; t < 4; t++)
                ldm_x4(af[t], sA + swzg(m0 + t * 16 + a_row, 2 * s + a_kc));
#pragma unroll
            for (int u2 = 0; u2 < 4; u2++) {
                uint32_t r4[4];
                ldm_x4(r4, sB + swzg(n0 + (u2 * 2 + b_sel) * 8 + b_row, 2 * s + b_kc));
                bf[u2*2][0] = r4[0]; bf[u2*2][1] = r4[1];
                bf[u2*2+1][0] = r4[2]; bf[u2*2+1][1] = r4[3];
            }
#pragma unroll
            for (int t = 0; t < 4; t++)
#pragma unroll
                for (int u = 0; u < 8; u++)
                    mma_f16(acc[t][u], af[t], bf[u]);
        }

        if (it + 3 < NITER) load_tile(it + 3, (it + 3) & 3);
        CP_COMMIT();
    }

    const int er = lane >> 2, ec = (lane & 3) * 2;
#pragma unroll
    for (int t = 0; t < 4; t++) {
#pragma unroll
        for (int u = 0; u < 8; u++) {
            int col = col0 + n0 + u * 8 + ec;
#pragma unroll
            for (int half_ = 0; half_ < 2; half_++) {
                int row = row0 + m0 + t * 16 + er + half_ * 8;
                float x = acc[t][u][half_*2] * scale, y = acc[t][u][half_*2+1] * scale;
                if (mode == 0) {
                    *(float2*)(C + (size_t)row * EE + col) = make_float2(x, y);
                } else {
                    int n = row >> 11, l = row & 2047;
                    int hh = col >> 6, d = col & 63;
                    size_t off = ((size_t)((n * HH + hh) * LQ + l)) * DD + d;
                    __half hx = __float2half_rn(x), hy = __float2half_rn(y);
                    __half lx = __float2half_rn(x - __half2float(hx));
                    __half ly = __float2half_rn(y - __half2float(hy));
                    __half hp[2] = {hx, hy}, lp[2] = {lx, ly};
                    *(uint32_t*)(Chi + off) = *(const uint32_t*)hp;
                    *(uint32_t*)(Clo + off) = *(const uint32_t*)lp;
                }
            }
        }
    }
}

// ---------------------------------------------------------------------------
// Flash attention, mma.sync fp16 — R7-PROVEN STRUCTURE:
//  QK^T: 3-product  qh*kh + qh*kl + ql*kh
//  PV:   2-product  p*(vh+vl)  (P fp16 single)
// Block = 128 q rows x one (n,h). 8 warps x 16 q rows. k-tiles of 64, 4-stage.
// smem: Qh 0, Ql 16K, stage s at 32K+s*32K: {Kh, Kl, Vh, Vl} x 8K.
// Only delta vs R7: epilogue emits fp16 hi/lo (was bf16).
// ---------------------------------------------------------------------------
__device__ __forceinline__ uint32_t swzf(int row, int ch) {  // 128B rows
    return (uint32_t)(row * 128 + ((ch ^ (row & 7)) << 4));
}
#define FLASH_SMEM (32768 + 4 * 32768)

__global__ __launch_bounds__(256)
void flash_mma()
{
    extern __shared__ char smf[];
    const uint32_t sb = (uint32_t)__cvta_generic_to_shared(smf);
    const int tid = threadIdx.x;
    const int wid = tid >> 5, lane = tid & 31;
    const int qb = 15 - (int)blockIdx.x;      // heavy blocks first
    const int nh = blockIdx.y;
    const int q0 = qb * 128;
    const int nkt = 2 * (qb + 1);

    const size_t hb = (size_t)nh * LQ * DD;
    const __half* Qhg = g_qh + hb; const __half* Qlg = g_ql + hb;
    const __half* Khg = g_kh + hb; const __half* Klg = g_kl + hb;
    const __half* Vhg = g_vh + hb; const __half* Vlg = g_vl + hb;

    // Q (hi+lo): 2048 16B chunks
#pragma unroll
    for (int j = 0; j < 8; j++) {
        int c = tid + j * 256;
        int tsr = c >> 10, cc = c & 1023, row = cc >> 3, ch = cc & 7;
        const __half* src = tsr ? Qlg : Qhg;
        cp16(sb + tsr * 16384 + swzf(row, ch), src + (size_t)(q0 + row) * DD + ch * 8);
    }
    CP_COMMIT();

    auto load_kv = [&](int jt, int s) {
        const int k0 = jt * 64;
        const uint32_t stb = sb + 32768 + s * 32768;
#pragma unroll
        for (int j = 0; j < 8; j++) {
            int c = tid + j * 256;
            int tsr = c >> 9, cc = c & 511, row = cc >> 3, ch = cc & 7;
            const __half* src = (tsr == 0) ? Khg : (tsr == 1) ? Klg : (tsr == 2) ? Vhg : Vlg;
            cp16(stb + tsr * 8192 + swzf(row, ch), src + (size_t)(k0 + row) * DD + ch * 8);
        }
    };
    load_kv(0, 0); CP_COMMIT();
    if (nkt > 1) load_kv(1, 1);
    CP_COMMIT();
    if (nkt > 2) load_kv(2, 2);
    CP_COMMIT();

    // hoist Q fragments
    CP_WAIT(3);
    __syncthreads();
    uint32_t qfh[4][4], qfl[4][4];
    {
        const int g = lane >> 3;
        const int qrow = wid * 16 + (lane & 7) + (g & 1) * 8;
#pragma unroll
        for (int kc = 0; kc < 4; kc++) {
            int ch = 2 * kc + (g >> 1);
            ldm_x4(qfh[kc], sb + swzf(qrow, ch));
            ldm_x4(qfl[kc], sb + 16384 + swzf(qrow, ch));
        }
    }

    float oacc[8][4];
#pragma unroll
    for (int u = 0; u < 8; u++)
#pragma unroll
        for (int e = 0; e < 4; e++) oacc[u][e] = 0.f;
    float m0 = -1e30f, m1 = -1e30f, l0 = 0.f, l1 = 0.f;

    const int qw_lo = q0 + wid * 16;
    const int qw_hi = qw_lo + 15;
    const int r0 = qw_lo + (lane >> 2), r1 = r0 + 8;
    const int b_row = lane & 7, b_sel = (lane >> 4) & 1, b_kc = (lane >> 3) & 1;
    const int vrow_base = (lane & 7) + ((lane >> 3) & 1) * 8;
    const int vch_off = lane >> 4;

    for (int it = 0; it < nkt; it++) {
        CP_WAIT(2);
        __syncthreads();
        const int k0 = it * 64;
        const uint32_t st = sb + 32768 + (it & 3) * 32768;

        if (k0 <= qw_hi) {
            // S = Q K^T (3-product fp16 split), into 8 n8-tiles
            float sacc[8][4];
#pragma unroll
            for (int u = 0; u < 8; u++)
#pragma unroll
                for (int e = 0; e < 4; e++) sacc[u][e] = 0.f;
#pragma unroll
            for (int kc = 0; kc < 4; kc++) {
                uint32_t kfh[4][4], kfl[4][4];
#pragma unroll
                for (int u2 = 0; u2 < 4; u2++) {
                    int r = (u2 * 2 + b_sel) * 8 + b_row;
                    int ch = 2 * kc + b_kc;
                    ldm_x4(kfh[u2], st + swzf(r, ch));
                    ldm_x4(kfl[u2], st + 8192 + swzf(r, ch));
                }
#pragma unroll
                for (int u2 = 0; u2 < 4; u2++) {
                    mma_f16(sacc[2*u2],   qfh[kc], &kfh[u2][0]);
                    mma_f16(sacc[2*u2],   qfh[kc], &kfl[u2][0]);
                    mma_f16(sacc[2*u2],   qfl[kc], &kfh[u2][0]);
                    mma_f16(sacc[2*u2+1], qfh[kc], &kfh[u2][2]);
                    mma_f16(sacc[2*u2+1], qfh[kc], &kfl[u2][2]);
                    mma_f16(sacc[2*u2+1], qfl[kc], &kfh[u2][2]);
                }
            }

            // causal mask
            if (k0 + 63 > qw_lo) {
#pragma unroll
                for (int u = 0; u < 8; u++) {
                    int c = k0 + u * 8 + 2 * (lane & 3);
                    if (c     > r0) sacc[u][0] = -1e30f;
                    if (c + 1 > r0) sacc[u][1] = -1e30f;
                    if (c     > r1) sacc[u][2] = -1e30f;
                    if (c + 1 > r1) sacc[u][3] = -1e30f;
                }
            }

            // online softmax (base-2)
            float mx0 = -1e30f, mx1 = -1e30f;
#pragma unroll
            for (int u = 0; u < 8; u++) {
                mx0 = fmaxf(mx0, fmaxf(sacc[u][0], sacc[u][1]));
                mx1 = fmaxf(mx1, fmaxf(sacc[u][2], sacc[u][3]));
            }
            mx0 = fmaxf(mx0, __shfl_xor_sync(0xffffffffu, mx0, 1));
            mx0 = fmaxf(mx0, __shfl_xor_sync(0xffffffffu, mx0, 2));
            mx1 = fmaxf(mx1, __shfl_xor_sync(0xffffffffu, mx1, 1));
            mx1 = fmaxf(mx1, __shfl_xor_sync(0xffffffffu, mx1, 2));
            float mn0 = fmaxf(m0, mx0), mn1 = fmaxf(m1, mx1);
            float a0 = exp2f(m0 - mn0), a1 = exp2f(m1 - mn1);
            float ls0 = 0.f, ls1 = 0.f;
#pragma unroll
            for (int u = 0; u < 8; u++) {
                sacc[u][0] = exp2f(sacc[u][0] - mn0);
                sacc[u][1] = exp2f(sacc[u][1] - mn0);
                sacc[u][2] = exp2f(sacc[u][2] - mn1);
                sacc[u][3] = exp2f(sacc[u][3] - mn1);
                ls0 += sacc[u][0] + sacc[u][1];
                ls1 += sacc[u][2] + sacc[u][3];
            }
            ls0 += __shfl_xor_sync(0xffffffffu, ls0, 1);
            ls0 += __shfl_xor_sync(0xffffffffu, ls0, 2);
            ls1 += __shfl_xor_sync(0xffffffffu, ls1, 1);
            ls1 += __shfl_xor_sync(0xffffffffu, ls1, 2);
            l0 = l0 * a0 + ls0; l1 = l1 * a1 + ls1;
            m0 = mn0; m1 = mn1;
#pragma unroll
            for (int u = 0; u < 8; u++) {
                oacc[u][0] *= a0; oacc[u][1] *= a0;
                oacc[u][2] *= a1; oacc[u][3] *= a1;
            }

            // O += P V (P fp16 single + V hi/lo)
#pragma unroll
            for (int kc = 0; kc < 4; kc++) {
                uint32_t ah[4];
#pragma unroll
                for (int half_ = 0; half_ < 2; half_++) {
                    const float* s4 = sacc[2 * kc + half_];
                    ah[2*half_]   = packh2(s4[0], s4[1]);
                    ah[2*half_+1] = packh2(s4[2], s4[3]);
                }
#pragma unroll
                for (int dnp = 0; dnp < 4; dnp++) {
                    uint32_t vfh[4], vfl[4];
                    int vr = 16 * kc + vrow_base;
                    int vc = 2 * dnp + vch_off;
                    ldm_x4t(vfh, st + 16384 + swzf(vr, vc));
                    ldm_x4t(vfl, st + 24576 + swzf(vr, vc));
                    mma_f16(oacc[2*dnp],   ah, &vfh[0]);
                    mma_f16(oacc[2*dnp],   ah, &vfl[0]);
                    mma_f16(oacc[2*dnp+1], ah, &vfh[2]);
                    mma_f16(oacc[2*dnp+1], ah, &vfl[2]);
                }
            }
        }

        if (it + 3 < nkt) load_kv(it + 3, (it + 3) & 3);
        CP_COMMIT();
    }

    // epilogue: normalize, fp16 hi/lo split, write head-interleaved [n][q][EE]
    const int n = nh / HH, hd = nh % HH;
    const float il0 = 1.f / l0, il1 = 1.f / l1;
#pragma unroll
    for (int u = 0; u < 8; u++) {
        int d = hd * DD + u * 8 + 2 * (lane & 3);
#pragma unroll
        for (int half_ = 0; half_ < 2; half_++) {
            int row = half_ ? r1 : r0;
            float il = half_ ? il1 : il0;
            float x = oacc[u][2*half_] * il, y = oacc[u][2*half_+1] * il;
            __half hx = __float2half_rn(x), hy = __float2half_rn(y);
            __half lx = __float2half_rn(x - __half2float(hx));
            __half ly = __float2half_rn(y - __half2float(hy));
            __half hp[2] = {hx, hy}, lp[2] = {lx, ly};
            size_t off = ((size_t)(n * LQ + row)) * EE + d;
            *(uint32_t*)(g_ahi + off) = *(const uint32_t*)hp;
            *(uint32_t*)(g_alo + off) = *(const uint32_t*)lp;
        }
    }
}

// ---------------------------------------------------------------------------
extern "C" void kernel_launch(void* const* d_in, const int* in_sizes, int n_in,
                              void* d_out, int out_size)
{
    (void)in_sizes; (void)n_in; (void)out_size;
    const float* q  = (const float*)d_in[0];
    const float* k  = (const float*)d_in[1];
    const float* v  = (const float*)d_in[2];
    const float* wq = (const float*)d_in[3];
    const float* wk = (const float*)d_in[4];
    const float* wv = (const float*)d_in[5];
    const float* wo = (const float*)d_in[6];
    float* out = (float*)d_out;

    __half *xhi, *whi, *wlo, *ahi;
    __half *qh, *ql, *kh, *kl, *vh, *vl;
    cudaGetSymbolAddress((void**)&xhi, g_xhi);
    cudaGetSymbolAddress((void**)&whi, g_whi);
    cudaGetSymbolAddress((void**)&wlo, g_wlo);
    cudaGetSymbolAddress((void**)&ahi, g_ahi);
    cudaGetSymbolAddress((void**)&qh,  g_qh);
    cudaGetSymbolAddress((void**)&ql,  g_ql);
    cudaGetSymbolAddress((void**)&kh,  g_kh);
    cudaGetSymbolAddress((void**)&kl,  g_kl);
    cudaGetSymbolAddress((void**)&vh,  g_vh);
    cudaGetSymbolAddress((void**)&vl,  g_vl);

    cudaFuncSetAttribute(gemm_mma, cudaFuncAttributeMaxDynamicSharedMemorySize, GEMM_SMEM);
    cudaFuncSetAttribute(flash_mma, cudaFuncAttributeMaxDynamicSharedMemorySize, FLASH_SMEM);

    const size_t NX = (size_t)NL * GK;
    const size_t NW = (size_t)GK * GK;
    const int TB = 256;
    const int n4x = (int)(NX / 4), n4w = (int)(NW / 4);

    // launch order: flash_mma is my-launch #5 == ncu-captured slot
    split_all<<<dim3((n4x + TB - 1) / TB, 7), TB>>>(q, k, v, wq, wk, wv, wo, n4x, n4w);

    dim3 gg(EE / 128, NL / 128);
    gemm_mma<<<gg, 128, GEMM_SMEM>>>(xhi,          whi,          wlo,
                                     nullptr, qh, ql, 1, QSCALE);
    gemm_mma<<<gg, 128, GEMM_SMEM>>>(xhi + NX,     whi + NW,     wlo + NW,
                                     nullptr, kh, kl, 1, 1.0f);
    gemm_mma<<<gg, 128, GEMM_SMEM>>>(xhi + 2*NX,   whi + 2*NW,   wlo + 2*NW,
                                     nullptr, vh, vl, 1, 1.0f);

    flash_mma<<<dim3(16, NB * HH), 256, FLASH_SMEM>>>();

    gemm_mma<<<gg, 128, GEMM_SMEM>>>(ahi, whi + 3*NW, wlo + 3*NW,
                                     out, nullptr, nullptr, 0, 1.0f);
}